// round 3
// baseline (speedup 1.0000x reference)
#include <cuda_runtime.h>
#include <cuda_bf16.h>

#define N_NODES 20000
#define N_EDGES 640000
#define HID     128
#define N_GRAPHS 32
#define OUT_DIM 3

// ---------------- scratch (static device globals; no allocation) -------------
__device__ float g_h     [N_NODES * HID];   // x @ W_gcn
__device__ float g_hgcn  [N_NODES * HID];   // after GCN agg + relu
__device__ float g_neigh [N_NODES * HID];   // SAGE mean-aggregated neighbors
__device__ float g_hsage [N_NODES * HID];   // after SAGE + relu
__device__ float g_dinv  [N_NODES];
__device__ int   g_cnt   [N_NODES];         // incoming-edge count (no self loop)
__device__ int   g_off   [N_NODES + 1];
__device__ int   g_cursor[N_NODES];
__device__ int   g_csr   [N_EDGES];         // source node per CSR slot
__device__ float g_pooled[N_GRAPHS * HID];
__device__ int   g_is64;                    // 1 if indices are int64, else int32

__device__ __forceinline__ int clampi(int v, int lo, int hi) {
    return v < lo ? lo : (v > hi ? hi : v);
}

// index accessor honoring detected dtype; clamped for safety
__device__ __forceinline__ int idx_at(const void* p, long long i, int hi) {
    int v = g_is64 ? (int)((const long long*)p)[i] : ((const int*)p)[i];
    return clampi(v, 0, hi);
}

// ---------------- kernels ----------------------------------------------------

// Detect int64 vs int32: for int64 little-endian values < 2^31, every odd
// 32-bit word is 0. Random int32 indices make 16 consecutive zeros impossible.
__global__ void k_detect(const int* __restrict__ eraw) {
    if (threadIdx.x == 0) {
        int all_zero = 1;
        #pragma unroll
        for (int i = 0; i < 32; i += 2)
            if (eraw[i + 1] != 0) { all_zero = 0; break; }
        g_is64 = all_zero;
    }
}

__global__ void k_zero() {
    int i = blockIdx.x * blockDim.x + threadIdx.x;
    int stride = gridDim.x * blockDim.x;
    for (int j = i; j < N_NODES; j += stride) { g_cnt[j] = 0; g_cursor[j] = 0; }
    for (int j = i; j < N_GRAPHS * HID; j += stride) g_pooled[j] = 0.f;
}

__global__ void k_count(const void* __restrict__ eidx) {
    int e = blockIdx.x * blockDim.x + threadIdx.x;
    if (e < N_EDGES) {
        int c = idx_at(eidx, (long long)N_EDGES + e, N_NODES - 1);  // col
        atomicAdd(&g_cnt[c], 1);
    }
}

// single-block exclusive scan over 20000 counts
__global__ void k_scan() {
    __shared__ int sh[1024];
    __shared__ int carry;
    int t = threadIdx.x;
    if (t == 0) carry = 0;
    __syncthreads();
    for (int base = 0; base < N_NODES; base += 1024) {
        int i = base + t;
        int v = (i < N_NODES) ? g_cnt[i] : 0;
        sh[t] = v;
        __syncthreads();
        for (int s = 1; s < 1024; s <<= 1) {
            int add = (t >= s) ? sh[t - s] : 0;
            __syncthreads();
            sh[t] += add;
            __syncthreads();
        }
        if (i < N_NODES) g_off[i] = carry + sh[t] - v;  // exclusive
        __syncthreads();
        if (t == 1023) carry += sh[1023];
        __syncthreads();
    }
    if (t == 0) g_off[N_NODES] = carry;
}

__global__ void k_dinv() {
    int i = blockIdx.x * blockDim.x + threadIdx.x;
    if (i < N_NODES) g_dinv[i] = rsqrtf((float)(g_cnt[i] + 1));  // +1 self loop
}

__global__ void k_fill(const void* __restrict__ eidx) {
    int e = blockIdx.x * blockDim.x + threadIdx.x;
    if (e < N_EDGES) {
        int r = idx_at(eidx, e, N_NODES - 1);                        // row (src)
        int c = idx_at(eidx, (long long)N_EDGES + e, N_NODES - 1);   // col (dst)
        int pos = g_off[c] + atomicAdd(&g_cursor[c], 1);
        if (pos >= 0 && pos < N_EDGES) g_csr[pos] = r;
    }
}

// g_h[20000,128] = X[20000,128] @ W[128,128]; 8 rows per block, 128 threads
__global__ void k_gemm1(const float* __restrict__ X, const float* __restrict__ W) {
    __shared__ float xs[8][HID];
    int r0 = blockIdx.x * 8;
    int t = threadIdx.x;
    #pragma unroll
    for (int r = 0; r < 8; r++) xs[r][t] = X[(size_t)(r0 + r) * HID + t];
    __syncthreads();
    float acc[8] = {0.f, 0.f, 0.f, 0.f, 0.f, 0.f, 0.f, 0.f};
    #pragma unroll 8
    for (int k = 0; k < HID; k++) {
        float w = W[k * HID + t];
        #pragma unroll
        for (int r = 0; r < 8; r++) acc[r] = fmaf(xs[r][k], w, acc[r]);
    }
    #pragma unroll
    for (int r = 0; r < 8; r++) g_h[(size_t)(r0 + r) * HID + t] = acc[r];
}

// GCN gather: one warp per node, float4 per lane (32 lanes x 4 = 128 feats)
__global__ void k_gcn_agg(const float* __restrict__ b_gcn) {
    int warp = (blockIdx.x * blockDim.x + threadIdx.x) >> 5;
    int lane = threadIdx.x & 31;
    if (warp >= N_NODES) return;
    int v = warp;
    float dv = g_dinv[v];
    float4 acc = ((const float4*)(g_h + (size_t)v * HID))[lane];
    float wself = dv * dv;
    acc.x *= wself; acc.y *= wself; acc.z *= wself; acc.w *= wself;
    int beg = g_off[v], end = g_off[v + 1];
    for (int i = beg; i < end; i++) {
        int s = g_csr[i];
        float w = g_dinv[s] * dv;
        float4 hs = ((const float4*)(g_h + (size_t)s * HID))[lane];
        acc.x = fmaf(hs.x, w, acc.x);
        acc.y = fmaf(hs.y, w, acc.y);
        acc.z = fmaf(hs.z, w, acc.z);
        acc.w = fmaf(hs.w, w, acc.w);
    }
    float4 b4 = ((const float4*)b_gcn)[lane];
    acc.x = fmaxf(acc.x + b4.x, 0.f);
    acc.y = fmaxf(acc.y + b4.y, 0.f);
    acc.z = fmaxf(acc.z + b4.z, 0.f);
    acc.w = fmaxf(acc.w + b4.w, 0.f);
    ((float4*)(g_hgcn + (size_t)v * HID))[lane] = acc;
}

// SAGE mean aggregation: neigh[v] = sum(h_gcn[src]) / max(cnt,1)
__global__ void k_sage_agg() {
    int warp = (blockIdx.x * blockDim.x + threadIdx.x) >> 5;
    int lane = threadIdx.x & 31;
    if (warp >= N_NODES) return;
    int v = warp;
    float4 acc = make_float4(0.f, 0.f, 0.f, 0.f);
    int beg = g_off[v], end = g_off[v + 1];
    for (int i = beg; i < end; i++) {
        int s = g_csr[i];
        float4 hs = ((const float4*)(g_hgcn + (size_t)s * HID))[lane];
        acc.x += hs.x; acc.y += hs.y; acc.z += hs.z; acc.w += hs.w;
    }
    float inv = 1.f / fmaxf((float)(end - beg), 1.f);
    acc.x *= inv; acc.y *= inv; acc.z *= inv; acc.w *= inv;
    ((float4*)(g_neigh + (size_t)v * HID))[lane] = acc;
}

// h_sage = relu(neigh @ Wl + h_gcn @ Wr + b)
__global__ void k_gemm2(const float* __restrict__ Wl, const float* __restrict__ Wr,
                        const float* __restrict__ b) {
    __shared__ float ns[8][HID];
    __shared__ float hs[8][HID];
    int r0 = blockIdx.x * 8;
    int t = threadIdx.x;
    #pragma unroll
    for (int r = 0; r < 8; r++) {
        ns[r][t] = g_neigh[(size_t)(r0 + r) * HID + t];
        hs[r][t] = g_hgcn [(size_t)(r0 + r) * HID + t];
    }
    __syncthreads();
    float acc[8];
    float bt = b[t];
    #pragma unroll
    for (int r = 0; r < 8; r++) acc[r] = bt;
    #pragma unroll 4
    for (int k = 0; k < HID; k++) {
        float wl = Wl[k * HID + t];
        float wr = Wr[k * HID + t];
        #pragma unroll
        for (int r = 0; r < 8; r++) {
            acc[r] = fmaf(ns[r][k], wl, acc[r]);
            acc[r] = fmaf(hs[r][k], wr, acc[r]);
        }
    }
    #pragma unroll
    for (int r = 0; r < 8; r++)
        g_hsage[(size_t)(r0 + r) * HID + t] = fmaxf(acc[r], 0.f);
}

// global_add_pool: batch is sorted; accumulate in registers, flush on change
#define POOL_NODES 160
__global__ void k_pool(const void* __restrict__ batch) {
    int t = threadIdx.x;           // feature index, 128 threads
    int n0 = blockIdx.x * POOL_NODES;
    int n1 = n0 + POOL_NODES; if (n1 > N_NODES) n1 = N_NODES;
    if (n0 >= N_NODES) return;
    float acc = 0.f;
    int cur = idx_at(batch, n0, N_GRAPHS - 1);
    for (int v = n0; v < n1; v++) {
        int g = idx_at(batch, v, N_GRAPHS - 1);
        if (g != cur) {
            atomicAdd(&g_pooled[cur * HID + t], acc);
            acc = 0.f; cur = g;
        }
        acc += g_hsage[(size_t)v * HID + t];
    }
    atomicAdd(&g_pooled[cur * HID + t], acc);
}

// MLP head: out[g] = relu(pooled[g] @ Wfc1 + b1) @ Wfc2 + b2
__global__ void k_head(const float* __restrict__ Wfc1, const float* __restrict__ b1,
                       const float* __restrict__ Wfc2, const float* __restrict__ b2,
                       float* __restrict__ out) {
    __shared__ float hid[HID];
    int g = blockIdx.x;
    int t = threadIdx.x;
    float acc = b1[t];
    #pragma unroll 8
    for (int k = 0; k < HID; k++)
        acc = fmaf(g_pooled[g * HID + k], Wfc1[k * HID + t], acc);
    hid[t] = fmaxf(acc, 0.f);
    __syncthreads();
    if (t < OUT_DIM) {
        float o = b2[t];
        #pragma unroll 8
        for (int k = 0; k < HID; k++)
            o = fmaf(hid[k], Wfc2[k * OUT_DIM + t], o);
        out[g * OUT_DIM + t] = o;
    }
}

// ---------------- launch ------------------------------------------------------
extern "C" void kernel_launch(void* const* d_in, const int* in_sizes, int n_in,
                              void* d_out, int out_size) {
    // Default mapping: metadata follows setup_inputs() insertion order.
    // Sanity: x has 2,560,000 elements; if it's not at slot 0, assume
    // alphabetical ordering (W_fc1,W_fc2,W_gcn,W_sage_l,W_sage_r,
    // b_fc1,b_fc2,b_gcn,b_sage,batch,edge_index,x).
    int map[12] = {0,1,2,3,4,5,6,7,8,9,10,11};
    if (n_in >= 12 && in_sizes[0] != 2560000) {
        // my slot:   x  eidx batch Wg  bg  Wsl Wsr bs  Wf1 bf1 Wf2 bf2
        const int alpha[12] = {11, 10,  9,  2,  7,  3,  4,  8,  0,  5,  1,  6};
        for (int i = 0; i < 12; i++) map[i] = alpha[i];
    }
    const float* x      = (const float*)d_in[map[0]];
    const void*  eidx   = d_in[map[1]];
    const void*  batch  = d_in[map[2]];
    const float* W_gcn  = (const float*)d_in[map[3]];
    const float* b_gcn  = (const float*)d_in[map[4]];
    const float* W_sl   = (const float*)d_in[map[5]];
    const float* W_sr   = (const float*)d_in[map[6]];
    const float* b_sage = (const float*)d_in[map[7]];
    const float* W_fc1  = (const float*)d_in[map[8]];
    const float* b_fc1  = (const float*)d_in[map[9]];
    const float* W_fc2  = (const float*)d_in[map[10]];
    const float* b_fc2  = (const float*)d_in[map[11]];
    float* out = (float*)d_out;

    k_detect<<<1, 32>>>((const int*)eidx);
    k_zero<<<256, 256>>>();
    k_count<<<(N_EDGES + 255) / 256, 256>>>(eidx);
    k_scan<<<1, 1024>>>();
    k_dinv<<<(N_NODES + 255) / 256, 256>>>();
    k_fill<<<(N_EDGES + 255) / 256, 256>>>(eidx);

    k_gemm1<<<N_NODES / 8, HID>>>(x, W_gcn);                 // h = x @ W_gcn
    k_gcn_agg<<<(N_NODES * 32 + 255) / 256, 256>>>(b_gcn);   // GCN agg + relu
    k_sage_agg<<<(N_NODES * 32 + 255) / 256, 256>>>();       // mean neighbors
    k_gemm2<<<N_NODES / 8, HID>>>(W_sl, W_sr, b_sage);       // SAGE + relu
    k_pool<<<(N_NODES + POOL_NODES - 1) / POOL_NODES, HID>>>(batch);
    k_head<<<N_GRAPHS, HID>>>(W_fc1, b_fc1, W_fc2, b_fc2, out);
}

// round 4
// speedup vs baseline: 1.4442x; 1.4442x over previous
#include <cuda_runtime.h>
#include <cuda_bf16.h>

#define N_NODES 20000
#define N_EDGES 640000
#define HID     128
#define N_GRAPHS 32
#define OUT_DIM 3
#define NBLK    ((N_NODES + 127) / 128)   // 157 scan blocks

// ---------------- scratch (static device globals; no allocation) -------------
__device__ float g_h     [N_NODES * HID];   // (x @ W_gcn) * dinv  (pre-scaled)
__device__ float g_hgcn  [N_NODES * HID];   // after GCN agg + relu
__device__ float g_neigh [N_NODES * HID];   // SAGE mean-aggregated neighbors
__device__ float g_dinv  [N_NODES];
__device__ int   g_cnt   [N_NODES];         // incoming-edge count (no self loop)
__device__ int   g_off   [N_NODES + 1];
__device__ int   g_cursor[N_NODES];
__device__ int   g_csr   [N_EDGES];         // source node per CSR slot
__device__ int   g_bsum  [NBLK];
__device__ int   g_boff  [NBLK];
__device__ float g_pooled[N_GRAPHS * HID];
__device__ int   g_is64;                    // 1 if indices are int64, else int32

__device__ __forceinline__ int clampi(int v, int lo, int hi) {
    return v < lo ? lo : (v > hi ? hi : v);
}
__device__ __forceinline__ int idx_at(const void* p, long long i, int hi) {
    int v = g_is64 ? (int)((const long long*)p)[i] : ((const int*)p)[i];
    return clampi(v, 0, hi);
}

// ---------------- CSR construction -------------------------------------------

__global__ void k_detect(const int* __restrict__ eraw) {
    if (threadIdx.x == 0) {
        int all_zero = 1;
        #pragma unroll
        for (int i = 0; i < 32; i += 2)
            if (eraw[i + 1] != 0) { all_zero = 0; break; }
        g_is64 = all_zero;
    }
}

__global__ void k_zero() {
    int i = blockIdx.x * blockDim.x + threadIdx.x;
    int stride = gridDim.x * blockDim.x;
    for (int j = i; j < N_NODES; j += stride) { g_cnt[j] = 0; g_cursor[j] = 0; }
    for (int j = i; j < N_GRAPHS * HID; j += stride) g_pooled[j] = 0.f;
}

__global__ void k_count(const void* __restrict__ eidx) {
    int e = blockIdx.x * blockDim.x + threadIdx.x;
    if (e < N_EDGES) {
        int c = idx_at(eidx, (long long)N_EDGES + e, N_NODES - 1);  // col
        atomicAdd(&g_cnt[c], 1);
    }
}

// per-block (128-wide) exclusive scan via warp shuffles; block totals out
__global__ void k_blockscan() {
    int t = threadIdx.x;
    int i = blockIdx.x * 128 + t;
    int v = (i < N_NODES) ? g_cnt[i] : 0;
    int lane = t & 31, w = t >> 5;
    int inc = v;
    #pragma unroll
    for (int s = 1; s < 32; s <<= 1) {
        int n = __shfl_up_sync(0xffffffffu, inc, s);
        if (lane >= s) inc += n;
    }
    __shared__ int wsum[4];
    if (lane == 31) wsum[w] = inc;
    __syncthreads();
    int woff = 0;
    #pragma unroll
    for (int j = 0; j < 4; j++) if (j < w) woff += wsum[j];
    if (i < N_NODES) g_off[i] = woff + inc - v;       // block-local exclusive
    if (t == 127) g_bsum[blockIdx.x] = woff + inc;    // block total
}

// scan the 157 block sums (single block, 256 threads)
__global__ void k_scanb() {
    int t = threadIdx.x;
    int v = (t < NBLK) ? g_bsum[t] : 0;
    int lane = t & 31, w = t >> 5;
    int inc = v;
    #pragma unroll
    for (int s = 1; s < 32; s <<= 1) {
        int n = __shfl_up_sync(0xffffffffu, inc, s);
        if (lane >= s) inc += n;
    }
    __shared__ int wsum[8];
    if (lane == 31) wsum[w] = inc;
    __syncthreads();
    int woff = 0;
    #pragma unroll
    for (int j = 0; j < 8; j++) if (j < w) woff += wsum[j];
    if (t < NBLK) g_boff[t] = woff + inc - v;         // exclusive
}

// add block offsets; fuse dinv computation
__global__ void k_addoff() {
    int t = threadIdx.x;
    int i = blockIdx.x * 128 + t;
    if (i < N_NODES) {
        g_off[i] += g_boff[blockIdx.x];
        g_dinv[i] = rsqrtf((float)(g_cnt[i] + 1));    // +1 self loop
    }
    if (i == 0) g_off[N_NODES] = N_EDGES;
}

__global__ void k_fill(const void* __restrict__ eidx) {
    int e = blockIdx.x * blockDim.x + threadIdx.x;
    if (e < N_EDGES) {
        int r = idx_at(eidx, e, N_NODES - 1);                        // src
        int c = idx_at(eidx, (long long)N_EDGES + e, N_NODES - 1);   // dst
        int pos = g_off[c] + atomicAdd(&g_cursor[c], 1);
        if (pos >= 0 && pos < N_EDGES) g_csr[pos] = r;
    }
}

// ---------------- compute -----------------------------------------------------

// g_h = (X @ W) * dinv  — 8 rows/block, 128 threads
__global__ void k_gemm1(const float* __restrict__ X, const float* __restrict__ W) {
    __shared__ float xs[8][HID];
    __shared__ float dv[8];
    int r0 = blockIdx.x * 8;
    int t = threadIdx.x;
    #pragma unroll
    for (int r = 0; r < 8; r++) xs[r][t] = X[(size_t)(r0 + r) * HID + t];
    if (t < 8) dv[t] = g_dinv[r0 + t];
    __syncthreads();
    float acc[8] = {0.f, 0.f, 0.f, 0.f, 0.f, 0.f, 0.f, 0.f};
    #pragma unroll 8
    for (int k = 0; k < HID; k++) {
        float w = W[k * HID + t];
        #pragma unroll
        for (int r = 0; r < 8; r++) acc[r] = fmaf(xs[r][k], w, acc[r]);
    }
    #pragma unroll
    for (int r = 0; r < 8; r++)
        g_h[(size_t)(r0 + r) * HID + t] = acc[r] * dv[r];
}

// GCN gather: h_gcn[v] = relu(dv * (sum_{s in N(v)} g_h[s] + g_h[v]) + b)
__global__ void k_gcn_agg(const float* __restrict__ b_gcn) {
    int warp = (blockIdx.x * blockDim.x + threadIdx.x) >> 5;
    int lane = threadIdx.x & 31;
    if (warp >= N_NODES) return;
    int v = warp;
    float dv = g_dinv[v];
    const float4* base = (const float4*)g_h;
    float4 acc = base[(size_t)v * 32 + lane];   // self (already dinv-scaled)
    int beg = g_off[v], end = g_off[v + 1];
    int i = beg;
    for (; i + 4 <= end; i += 4) {
        int s0 = g_csr[i], s1 = g_csr[i + 1], s2 = g_csr[i + 2], s3 = g_csr[i + 3];
        float4 a = base[(size_t)s0 * 32 + lane];
        float4 b = base[(size_t)s1 * 32 + lane];
        float4 c = base[(size_t)s2 * 32 + lane];
        float4 d = base[(size_t)s3 * 32 + lane];
        acc.x += (a.x + b.x) + (c.x + d.x);
        acc.y += (a.y + b.y) + (c.y + d.y);
        acc.z += (a.z + b.z) + (c.z + d.z);
        acc.w += (a.w + b.w) + (c.w + d.w);
    }
    for (; i < end; i++) {
        int s = g_csr[i];
        float4 a = base[(size_t)s * 32 + lane];
        acc.x += a.x; acc.y += a.y; acc.z += a.z; acc.w += a.w;
    }
    float4 b4 = ((const float4*)b_gcn)[lane];
    acc.x = fmaxf(fmaf(acc.x, dv, b4.x), 0.f);
    acc.y = fmaxf(fmaf(acc.y, dv, b4.y), 0.f);
    acc.z = fmaxf(fmaf(acc.z, dv, b4.z), 0.f);
    acc.w = fmaxf(fmaf(acc.w, dv, b4.w), 0.f);
    ((float4*)(g_hgcn + (size_t)v * HID))[lane] = acc;
}

// SAGE mean aggregation: neigh[v] = sum(h_gcn[src]) / max(cnt,1)
__global__ void k_sage_agg() {
    int warp = (blockIdx.x * blockDim.x + threadIdx.x) >> 5;
    int lane = threadIdx.x & 31;
    if (warp >= N_NODES) return;
    int v = warp;
    const float4* base = (const float4*)g_hgcn;
    float4 acc = make_float4(0.f, 0.f, 0.f, 0.f);
    int beg = g_off[v], end = g_off[v + 1];
    int i = beg;
    for (; i + 4 <= end; i += 4) {
        int s0 = g_csr[i], s1 = g_csr[i + 1], s2 = g_csr[i + 2], s3 = g_csr[i + 3];
        float4 a = base[(size_t)s0 * 32 + lane];
        float4 b = base[(size_t)s1 * 32 + lane];
        float4 c = base[(size_t)s2 * 32 + lane];
        float4 d = base[(size_t)s3 * 32 + lane];
        acc.x += (a.x + b.x) + (c.x + d.x);
        acc.y += (a.y + b.y) + (c.y + d.y);
        acc.z += (a.z + b.z) + (c.z + d.z);
        acc.w += (a.w + b.w) + (c.w + d.w);
    }
    for (; i < end; i++) {
        int s = g_csr[i];
        float4 a = base[(size_t)s * 32 + lane];
        acc.x += a.x; acc.y += a.y; acc.z += a.z; acc.w += a.w;
    }
    float inv = 1.f / fmaxf((float)(end - beg), 1.f);
    acc.x *= inv; acc.y *= inv; acc.z *= inv; acc.w *= inv;
    ((float4*)(g_neigh + (size_t)v * HID))[lane] = acc;
}

// h_sage = relu(neigh @ Wl + h_gcn @ Wr + b); pooling fused (batch sorted)
__global__ void k_gemm2(const float* __restrict__ Wl, const float* __restrict__ Wr,
                        const float* __restrict__ b, const void* __restrict__ batch) {
    __shared__ float ns[8][HID];
    __shared__ float hs[8][HID];
    __shared__ int bg[8];
    int r0 = blockIdx.x * 8;
    int t = threadIdx.x;
    #pragma unroll
    for (int r = 0; r < 8; r++) {
        ns[r][t] = g_neigh[(size_t)(r0 + r) * HID + t];
        hs[r][t] = g_hgcn [(size_t)(r0 + r) * HID + t];
    }
    if (t < 8) bg[t] = idx_at(batch, r0 + t, N_GRAPHS - 1);
    __syncthreads();
    float acc[8];
    float bt = b[t];
    #pragma unroll
    for (int r = 0; r < 8; r++) acc[r] = bt;
    #pragma unroll 4
    for (int k = 0; k < HID; k++) {
        float wl = Wl[k * HID + t];
        float wr = Wr[k * HID + t];
        #pragma unroll
        for (int r = 0; r < 8; r++) {
            acc[r] = fmaf(ns[r][k], wl, acc[r]);
            acc[r] = fmaf(hs[r][k], wr, acc[r]);
        }
    }
    // fused global_add_pool: accumulate per-graph runs, flush on change
    float psum = 0.f;
    int cur = bg[0];
    #pragma unroll
    for (int r = 0; r < 8; r++) {
        int g = bg[r];
        if (g != cur) {                       // uniform branch (bg in smem)
            atomicAdd(&g_pooled[cur * HID + t], psum);
            psum = 0.f; cur = g;
        }
        psum += fmaxf(acc[r], 0.f);
    }
    atomicAdd(&g_pooled[cur * HID + t], psum);
}

// MLP head: out[g] = relu(pooled[g] @ Wfc1 + b1) @ Wfc2 + b2
__global__ void k_head(const float* __restrict__ Wfc1, const float* __restrict__ b1,
                       const float* __restrict__ Wfc2, const float* __restrict__ b2,
                       float* __restrict__ out) {
    __shared__ float hid[HID];
    int g = blockIdx.x;
    int t = threadIdx.x;
    float acc = b1[t];
    #pragma unroll 8
    for (int k = 0; k < HID; k++)
        acc = fmaf(g_pooled[g * HID + k], Wfc1[k * HID + t], acc);
    hid[t] = fmaxf(acc, 0.f);
    __syncthreads();
    if (t < OUT_DIM) {
        float o = b2[t];
        #pragma unroll 8
        for (int k = 0; k < HID; k++)
            o = fmaf(hid[k], Wfc2[k * OUT_DIM + t], o);
        out[g * OUT_DIM + t] = o;
    }
}

// ---------------- launch ------------------------------------------------------
extern "C" void kernel_launch(void* const* d_in, const int* in_sizes, int n_in,
                              void* d_out, int out_size) {
    int map[12] = {0,1,2,3,4,5,6,7,8,9,10,11};
    if (n_in >= 12 && in_sizes[0] != 2560000) {
        const int alpha[12] = {11, 10,  9,  2,  7,  3,  4,  8,  0,  5,  1,  6};
        for (int i = 0; i < 12; i++) map[i] = alpha[i];
    }
    const float* x      = (const float*)d_in[map[0]];
    const void*  eidx   = d_in[map[1]];
    const void*  batch  = d_in[map[2]];
    const float* W_gcn  = (const float*)d_in[map[3]];
    const float* b_gcn  = (const float*)d_in[map[4]];
    const float* W_sl   = (const float*)d_in[map[5]];
    const float* W_sr   = (const float*)d_in[map[6]];
    const float* b_sage = (const float*)d_in[map[7]];
    const float* W_fc1  = (const float*)d_in[map[8]];
    const float* b_fc1  = (const float*)d_in[map[9]];
    const float* W_fc2  = (const float*)d_in[map[10]];
    const float* b_fc2  = (const float*)d_in[map[11]];
    float* out = (float*)d_out;

    k_detect<<<1, 32>>>((const int*)eidx);
    k_zero<<<160, 256>>>();
    k_count<<<(N_EDGES + 255) / 256, 256>>>(eidx);
    k_blockscan<<<NBLK, 128>>>();
    k_scanb<<<1, 256>>>();
    k_addoff<<<NBLK, 128>>>();
    k_fill<<<(N_EDGES + 255) / 256, 256>>>(eidx);

    k_gemm1<<<N_NODES / 8, HID>>>(x, W_gcn);                 // (x @ W_gcn)*dinv
    k_gcn_agg<<<(N_NODES * 32 + 255) / 256, 256>>>(b_gcn);   // GCN agg + relu
    k_sage_agg<<<(N_NODES * 32 + 255) / 256, 256>>>();       // mean neighbors
    k_gemm2<<<N_NODES / 8, HID>>>(W_sl, W_sr, b_sage, batch);// SAGE + relu + pool
    k_head<<<N_GRAPHS, HID>>>(W_fc1, b_fc1, W_fc2, b_fc2, out);
}

// round 5
// speedup vs baseline: 1.4862x; 1.0291x over previous
#include <cuda_runtime.h>
#include <cuda_fp16.h>

#define N_NODES 20000
#define N_EDGES 640000
#define HID     128
#define N_GRAPHS 32
#define OUT_DIM 3
#define NBLK    ((N_NODES + 127) / 128)   // 157 scan blocks

typedef struct { __half2 a, b; } half4_t;   // 8 bytes: 4 half features

// ---------------- scratch (static device globals; no allocation) -------------
__device__ __half g_hh    [N_NODES * HID];  // (x @ W_gcn) * dinv, fp16
__device__ __half g_hgcnh [N_NODES * HID];  // relu(GCN), fp16
__device__ __half g_neighh[N_NODES * HID];  // SAGE mean neighbors, fp16
__device__ float  g_dinv  [N_NODES];
__device__ int    g_cnt   [N_NODES];
__device__ int    g_off   [N_NODES + 1];
__device__ int    g_cursor[N_NODES];
__device__ int    g_csr   [N_EDGES];
__device__ int    g_bsum  [NBLK];
__device__ int    g_boff  [NBLK];
__device__ float  g_pooled[N_GRAPHS * HID];
__device__ int    g_is64;

__device__ __forceinline__ int clampi(int v, int lo, int hi) {
    return v < lo ? lo : (v > hi ? hi : v);
}
__device__ __forceinline__ int idx_at(const void* p, long long i, int hi) {
    int v = g_is64 ? (int)((const long long*)p)[i] : ((const int*)p)[i];
    return clampi(v, 0, hi);
}
__device__ __forceinline__ void acc4(float4& acc, half4_t h) {
    float2 lo = __half22float2(h.a);
    float2 hi = __half22float2(h.b);
    acc.x += lo.x; acc.y += lo.y; acc.z += hi.x; acc.w += hi.y;
}

// ---------------- CSR construction -------------------------------------------

__global__ void k_detect(const int* __restrict__ eraw) {
    if (threadIdx.x == 0) {
        int all_zero = 1;
        #pragma unroll
        for (int i = 0; i < 32; i += 2)
            if (eraw[i + 1] != 0) { all_zero = 0; break; }
        g_is64 = all_zero;
    }
}

__global__ void k_zero() {
    int i = blockIdx.x * blockDim.x + threadIdx.x;
    int stride = gridDim.x * blockDim.x;
    for (int j = i; j < N_NODES; j += stride) { g_cnt[j] = 0; g_cursor[j] = 0; }
    for (int j = i; j < N_GRAPHS * HID; j += stride) g_pooled[j] = 0.f;
}

__global__ void k_count(const void* __restrict__ eidx) {
    int e = blockIdx.x * blockDim.x + threadIdx.x;
    if (e < N_EDGES) {
        int c = idx_at(eidx, (long long)N_EDGES + e, N_NODES - 1);
        atomicAdd(&g_cnt[c], 1);
    }
}

__global__ void k_blockscan() {
    int t = threadIdx.x;
    int i = blockIdx.x * 128 + t;
    int v = (i < N_NODES) ? g_cnt[i] : 0;
    int lane = t & 31, w = t >> 5;
    int inc = v;
    #pragma unroll
    for (int s = 1; s < 32; s <<= 1) {
        int n = __shfl_up_sync(0xffffffffu, inc, s);
        if (lane >= s) inc += n;
    }
    __shared__ int wsum[4];
    if (lane == 31) wsum[w] = inc;
    __syncthreads();
    int woff = 0;
    #pragma unroll
    for (int j = 0; j < 4; j++) if (j < w) woff += wsum[j];
    if (i < N_NODES) g_off[i] = woff + inc - v;
    if (t == 127) g_bsum[blockIdx.x] = woff + inc;
}

__global__ void k_scanb() {
    int t = threadIdx.x;
    int v = (t < NBLK) ? g_bsum[t] : 0;
    int lane = t & 31, w = t >> 5;
    int inc = v;
    #pragma unroll
    for (int s = 1; s < 32; s <<= 1) {
        int n = __shfl_up_sync(0xffffffffu, inc, s);
        if (lane >= s) inc += n;
    }
    __shared__ int wsum[8];
    if (lane == 31) wsum[w] = inc;
    __syncthreads();
    int woff = 0;
    #pragma unroll
    for (int j = 0; j < 8; j++) if (j < w) woff += wsum[j];
    if (t < NBLK) g_boff[t] = woff + inc - v;
}

__global__ void k_addoff() {
    int t = threadIdx.x;
    int i = blockIdx.x * 128 + t;
    if (i < N_NODES) {
        g_off[i] += g_boff[blockIdx.x];
        g_dinv[i] = rsqrtf((float)(g_cnt[i] + 1));
    }
    if (i == 0) g_off[N_NODES] = N_EDGES;
}

__global__ void k_fill(const void* __restrict__ eidx) {
    int e = blockIdx.x * blockDim.x + threadIdx.x;
    if (e < N_EDGES) {
        int r = idx_at(eidx, e, N_NODES - 1);
        int c = idx_at(eidx, (long long)N_EDGES + e, N_NODES - 1);
        int pos = g_off[c] + atomicAdd(&g_cursor[c], 1);
        if (pos >= 0 && pos < N_EDGES) g_csr[pos] = r;
    }
}

// ---------------- compute -----------------------------------------------------

// g_hh = half((X @ W) * dinv) — 8 rows/block, 128 threads
__global__ void k_gemm1(const float* __restrict__ X, const float* __restrict__ W) {
    __shared__ float xs[8][HID];
    __shared__ float dv[8];
    int r0 = blockIdx.x * 8;
    int t = threadIdx.x;
    #pragma unroll
    for (int r = 0; r < 8; r++) xs[r][t] = X[(size_t)(r0 + r) * HID + t];
    if (t < 8) dv[t] = g_dinv[r0 + t];
    __syncthreads();
    float acc[8] = {0.f, 0.f, 0.f, 0.f, 0.f, 0.f, 0.f, 0.f};
    #pragma unroll 8
    for (int k = 0; k < HID; k++) {
        float w = W[k * HID + t];
        #pragma unroll
        for (int r = 0; r < 8; r++) acc[r] = fmaf(xs[r][k], w, acc[r]);
    }
    #pragma unroll
    for (int r = 0; r < 8; r++)
        g_hh[(size_t)(r0 + r) * HID + t] = __float2half_rn(acc[r] * dv[r]);
}

// GCN gather (fp16 rows, fp32 accum): h_gcn = relu(dv*(sum g_h[s] + g_h[v]) + b)
__global__ void k_gcn_agg(const float* __restrict__ b_gcn) {
    int warp = (blockIdx.x * blockDim.x + threadIdx.x) >> 5;
    int lane = threadIdx.x & 31;
    if (warp >= N_NODES) return;
    int v = warp;
    float dv = g_dinv[v];
    const half4_t* base = (const half4_t*)g_hh;     // 32 half4 per row
    float4 acc = make_float4(0.f, 0.f, 0.f, 0.f);
    acc4(acc, base[(size_t)v * 32 + lane]);         // self term
    int beg = g_off[v], end = g_off[v + 1];
    int i = beg;
    for (; i + 4 <= end; i += 4) {
        int s0 = g_csr[i], s1 = g_csr[i + 1], s2 = g_csr[i + 2], s3 = g_csr[i + 3];
        half4_t a = base[(size_t)s0 * 32 + lane];
        half4_t b = base[(size_t)s1 * 32 + lane];
        half4_t c = base[(size_t)s2 * 32 + lane];
        half4_t d = base[(size_t)s3 * 32 + lane];
        acc4(acc, a); acc4(acc, b); acc4(acc, c); acc4(acc, d);
    }
    for (; i < end; i++) acc4(acc, base[(size_t)g_csr[i] * 32 + lane]);
    float4 b4 = ((const float4*)b_gcn)[lane];
    float r0 = fmaxf(fmaf(acc.x, dv, b4.x), 0.f);
    float r1 = fmaxf(fmaf(acc.y, dv, b4.y), 0.f);
    float r2 = fmaxf(fmaf(acc.z, dv, b4.z), 0.f);
    float r3 = fmaxf(fmaf(acc.w, dv, b4.w), 0.f);
    half4_t o;
    o.a = __floats2half2_rn(r0, r1);
    o.b = __floats2half2_rn(r2, r3);
    ((half4_t*)g_hgcnh)[(size_t)v * 32 + lane] = o;
}

// SAGE mean aggregation (fp16 rows, fp32 accum)
__global__ void k_sage_agg() {
    int warp = (blockIdx.x * blockDim.x + threadIdx.x) >> 5;
    int lane = threadIdx.x & 31;
    if (warp >= N_NODES) return;
    int v = warp;
    const half4_t* base = (const half4_t*)g_hgcnh;
    float4 acc = make_float4(0.f, 0.f, 0.f, 0.f);
    int beg = g_off[v], end = g_off[v + 1];
    int i = beg;
    for (; i + 4 <= end; i += 4) {
        int s0 = g_csr[i], s1 = g_csr[i + 1], s2 = g_csr[i + 2], s3 = g_csr[i + 3];
        half4_t a = base[(size_t)s0 * 32 + lane];
        half4_t b = base[(size_t)s1 * 32 + lane];
        half4_t c = base[(size_t)s2 * 32 + lane];
        half4_t d = base[(size_t)s3 * 32 + lane];
        acc4(acc, a); acc4(acc, b); acc4(acc, c); acc4(acc, d);
    }
    for (; i < end; i++) acc4(acc, base[(size_t)g_csr[i] * 32 + lane]);
    float inv = 1.f / fmaxf((float)(end - beg), 1.f);
    half4_t o;
    o.a = __floats2half2_rn(acc.x * inv, acc.y * inv);
    o.b = __floats2half2_rn(acc.z * inv, acc.w * inv);
    ((half4_t*)g_neighh)[(size_t)v * 32 + lane] = o;
}

// h_sage = relu(neigh @ Wl + h_gcn @ Wr + b); pooling fused (batch sorted)
__global__ void k_gemm2(const float* __restrict__ Wl, const float* __restrict__ Wr,
                        const float* __restrict__ b, const void* __restrict__ batch) {
    __shared__ float ns[8][HID];
    __shared__ float hs[8][HID];
    __shared__ int bg[8];
    int r0 = blockIdx.x * 8;
    int t = threadIdx.x;
    #pragma unroll
    for (int r = 0; r < 8; r++) {
        ns[r][t] = __half2float(g_neighh[(size_t)(r0 + r) * HID + t]);
        hs[r][t] = __half2float(g_hgcnh [(size_t)(r0 + r) * HID + t]);
    }
    if (t < 8) bg[t] = idx_at(batch, r0 + t, N_GRAPHS - 1);
    __syncthreads();
    float acc[8];
    float bt = b[t];
    #pragma unroll
    for (int r = 0; r < 8; r++) acc[r] = bt;
    #pragma unroll 4
    for (int k = 0; k < HID; k++) {
        float wl = Wl[k * HID + t];
        float wr = Wr[k * HID + t];
        #pragma unroll
        for (int r = 0; r < 8; r++) {
            acc[r] = fmaf(ns[r][k], wl, acc[r]);
            acc[r] = fmaf(hs[r][k], wr, acc[r]);
        }
    }
    float psum = 0.f;
    int cur = bg[0];
    #pragma unroll
    for (int r = 0; r < 8; r++) {
        int g = bg[r];
        if (g != cur) {
            atomicAdd(&g_pooled[cur * HID + t], psum);
            psum = 0.f; cur = g;
        }
        psum += fmaxf(acc[r], 0.f);
    }
    atomicAdd(&g_pooled[cur * HID + t], psum);
}

// MLP head
__global__ void k_head(const float* __restrict__ Wfc1, const float* __restrict__ b1,
                       const float* __restrict__ Wfc2, const float* __restrict__ b2,
                       float* __restrict__ out) {
    __shared__ float hid[HID];
    int g = blockIdx.x;
    int t = threadIdx.x;
    float acc = b1[t];
    #pragma unroll 8
    for (int k = 0; k < HID; k++)
        acc = fmaf(g_pooled[g * HID + k], Wfc1[k * HID + t], acc);
    hid[t] = fmaxf(acc, 0.f);
    __syncthreads();
    if (t < OUT_DIM) {
        float o = b2[t];
        #pragma unroll 8
        for (int k = 0; k < HID; k++)
            o = fmaf(hid[k], Wfc2[k * OUT_DIM + t], o);
        out[g * OUT_DIM + t] = o;
    }
}

// ---------------- launch ------------------------------------------------------
extern "C" void kernel_launch(void* const* d_in, const int* in_sizes, int n_in,
                              void* d_out, int out_size) {
    int map[12] = {0,1,2,3,4,5,6,7,8,9,10,11};
    if (n_in >= 12 && in_sizes[0] != 2560000) {
        const int alpha[12] = {11, 10,  9,  2,  7,  3,  4,  8,  0,  5,  1,  6};
        for (int i = 0; i < 12; i++) map[i] = alpha[i];
    }
    const float* x      = (const float*)d_in[map[0]];
    const void*  eidx   = d_in[map[1]];
    const void*  batch  = d_in[map[2]];
    const float* W_gcn  = (const float*)d_in[map[3]];
    const float* b_gcn  = (const float*)d_in[map[4]];
    const float* W_sl   = (const float*)d_in[map[5]];
    const float* W_sr   = (const float*)d_in[map[6]];
    const float* b_sage = (const float*)d_in[map[7]];
    const float* W_fc1  = (const float*)d_in[map[8]];
    const float* b_fc1  = (const float*)d_in[map[9]];
    const float* W_fc2  = (const float*)d_in[map[10]];
    const float* b_fc2  = (const float*)d_in[map[11]];
    float* out = (float*)d_out;

    k_detect<<<1, 32>>>((const int*)eidx);
    k_zero<<<160, 256>>>();
    k_count<<<(N_EDGES + 255) / 256, 256>>>(eidx);
    k_blockscan<<<NBLK, 128>>>();
    k_scanb<<<1, 256>>>();
    k_addoff<<<NBLK, 128>>>();
    k_fill<<<(N_EDGES + 255) / 256, 256>>>(eidx);

    k_gemm1<<<N_NODES / 8, HID>>>(x, W_gcn);
    k_gcn_agg<<<(N_NODES * 32 + 255) / 256, 256>>>(b_gcn);
    k_sage_agg<<<(N_NODES * 32 + 255) / 256, 256>>>();
    k_gemm2<<<N_NODES / 8, HID>>>(W_sl, W_sr, b_sage, batch);
    k_head<<<N_GRAPHS, HID>>>(W_fc1, b_fc1, W_fc2, b_fc2, out);
}

// round 6
// speedup vs baseline: 1.6200x; 1.0900x over previous
#include <cuda_runtime.h>
#include <cuda_fp16.h>

#define N_NODES 20000
#define N_EDGES 640000
#define HID     128
#define N_GRAPHS 32
#define OUT_DIM 3
#define NBLK    ((N_NODES + 127) / 128)   // 157 scan blocks

typedef struct { __half2 a, b; } half4_t;   // 8 bytes: 4 half features

// ---------------- scratch (static device globals; no allocation) -------------
__device__ __half g_hh    [N_NODES * HID];  // (x @ W_gcn) * dinv, fp16
__device__ __half g_hgcnh [N_NODES * HID];  // relu(GCN), fp16
__device__ float  g_dinv  [N_NODES];
__device__ int    g_cnt   [N_NODES];
__device__ int    g_off   [N_NODES + 1];
__device__ int    g_csr   [N_EDGES];
__device__ int    g_bsum  [NBLK];
__device__ float  g_pooled[N_GRAPHS * HID];
__device__ int    g_is64;

__device__ __forceinline__ int clampi(int v, int lo, int hi) {
    return v < lo ? lo : (v > hi ? hi : v);
}
__device__ __forceinline__ int idx_at(const void* p, long long i, int hi) {
    int v = g_is64 ? (int)((const long long*)p)[i] : ((const int*)p)[i];
    return clampi(v, 0, hi);
}
__device__ __forceinline__ void acc4(float4& acc, half4_t h) {
    float2 lo = __half22float2(h.a);
    float2 hi = __half22float2(h.b);
    acc.x += lo.x; acc.y += lo.y; acc.z += hi.x; acc.w += hi.y;
}

// ---------------- CSR construction -------------------------------------------

// detect dtype + zero counters/pool (fused)
__global__ void k_init(const int* __restrict__ eraw) {
    int i = blockIdx.x * blockDim.x + threadIdx.x;
    if (i == 0) {
        int all_zero = 1;
        #pragma unroll
        for (int j = 0; j < 32; j += 2)
            if (eraw[j + 1] != 0) { all_zero = 0; break; }
        g_is64 = all_zero;
    }
    int stride = gridDim.x * blockDim.x;
    for (int j = i; j < N_NODES; j += stride) g_cnt[j] = 0;
    for (int j = i; j < N_GRAPHS * HID; j += stride) g_pooled[j] = 0.f;
}

__global__ void k_count(const void* __restrict__ eidx) {
    int e = blockIdx.x * blockDim.x + threadIdx.x;
    if (e < N_EDGES) {
        int c = idx_at(eidx, (long long)N_EDGES + e, N_NODES - 1);
        atomicAdd(&g_cnt[c], 1);
    }
}

// per-block (128-wide) exclusive scan via warp shuffles; block totals out
__global__ void k_blockscan() {
    int t = threadIdx.x;
    int i = blockIdx.x * 128 + t;
    int v = (i < N_NODES) ? g_cnt[i] : 0;
    int lane = t & 31, w = t >> 5;
    int inc = v;
    #pragma unroll
    for (int s = 1; s < 32; s <<= 1) {
        int n = __shfl_up_sync(0xffffffffu, inc, s);
        if (lane >= s) inc += n;
    }
    __shared__ int wsum[4];
    if (lane == 31) wsum[w] = inc;
    __syncthreads();
    int woff = 0;
    #pragma unroll
    for (int j = 0; j < 4; j++) if (j < w) woff += wsum[j];
    if (i < N_NODES) g_off[i] = woff + inc - v;
    if (t == 127) g_bsum[blockIdx.x] = woff + inc;
}

// add block offset (reduce own prefix of block sums inline) + dinv (fused)
__global__ void k_addoff() {
    __shared__ int red[4];
    __shared__ int boff;
    int t = threadIdx.x;
    int bid = blockIdx.x;
    int partial = 0;
    for (int j = t; j < bid; j += 128) partial += g_bsum[j];
    int lane = t & 31, w = t >> 5;
    #pragma unroll
    for (int s = 16; s > 0; s >>= 1)
        partial += __shfl_down_sync(0xffffffffu, partial, s);
    if (lane == 0) red[w] = partial;
    __syncthreads();
    if (t == 0) boff = red[0] + red[1] + red[2] + red[3];
    __syncthreads();
    int i = bid * 128 + t;
    if (i < N_NODES) {
        g_off[i] += boff;
        g_dinv[i] = rsqrtf((float)(g_cnt[i] + 1));   // +1 self loop
    }
    if (i == 0) g_off[N_NODES] = N_EDGES;
}

// fill CSR, consuming g_cnt as the per-node cursor (counts down)
__global__ void k_fill(const void* __restrict__ eidx) {
    int e = blockIdx.x * blockDim.x + threadIdx.x;
    if (e < N_EDGES) {
        int r = idx_at(eidx, e, N_NODES - 1);
        int c = idx_at(eidx, (long long)N_EDGES + e, N_NODES - 1);
        int pos = g_off[c] + atomicAdd(&g_cnt[c], -1) - 1;
        if (pos >= 0 && pos < N_EDGES) g_csr[pos] = r;
    }
}

// ---------------- compute -----------------------------------------------------

// g_hh = half((X @ W) * dinv) — 8 rows/block, 128 threads
__global__ void k_gemm1(const float* __restrict__ X, const float* __restrict__ W) {
    __shared__ float xs[8][HID];
    __shared__ float dv[8];
    int r0 = blockIdx.x * 8;
    int t = threadIdx.x;
    #pragma unroll
    for (int r = 0; r < 8; r++) xs[r][t] = X[(size_t)(r0 + r) * HID + t];
    if (t < 8) dv[t] = g_dinv[r0 + t];
    __syncthreads();
    float acc[8] = {0.f, 0.f, 0.f, 0.f, 0.f, 0.f, 0.f, 0.f};
    #pragma unroll 8
    for (int k = 0; k < HID; k++) {
        float w = W[k * HID + t];
        #pragma unroll
        for (int r = 0; r < 8; r++) acc[r] = fmaf(xs[r][k], w, acc[r]);
    }
    #pragma unroll
    for (int r = 0; r < 8; r++)
        g_hh[(size_t)(r0 + r) * HID + t] = __float2half_rn(acc[r] * dv[r]);
}

// GCN gather (fp16 rows, fp32 accum, 8-deep MLP)
__global__ void k_gcn_agg(const float* __restrict__ b_gcn) {
    int warp = (blockIdx.x * blockDim.x + threadIdx.x) >> 5;
    int lane = threadIdx.x & 31;
    if (warp >= N_NODES) return;
    int v = warp;
    float dv = g_dinv[v];
    const half4_t* base = (const half4_t*)g_hh;
    float4 acc = make_float4(0.f, 0.f, 0.f, 0.f);
    acc4(acc, base[(size_t)v * 32 + lane]);         // self term
    int beg = g_off[v], end = g_off[v + 1];
    int i = beg;
    for (; i + 8 <= end; i += 8) {
        int s0 = g_csr[i],     s1 = g_csr[i + 1], s2 = g_csr[i + 2], s3 = g_csr[i + 3];
        int s4 = g_csr[i + 4], s5 = g_csr[i + 5], s6 = g_csr[i + 6], s7 = g_csr[i + 7];
        half4_t a = base[(size_t)s0 * 32 + lane];
        half4_t b = base[(size_t)s1 * 32 + lane];
        half4_t c = base[(size_t)s2 * 32 + lane];
        half4_t d = base[(size_t)s3 * 32 + lane];
        half4_t e = base[(size_t)s4 * 32 + lane];
        half4_t f = base[(size_t)s5 * 32 + lane];
        half4_t g = base[(size_t)s6 * 32 + lane];
        half4_t h = base[(size_t)s7 * 32 + lane];
        acc4(acc, a); acc4(acc, b); acc4(acc, c); acc4(acc, d);
        acc4(acc, e); acc4(acc, f); acc4(acc, g); acc4(acc, h);
    }
    for (; i < end; i++) acc4(acc, base[(size_t)g_csr[i] * 32 + lane]);
    float4 b4 = ((const float4*)b_gcn)[lane];
    float r0 = fmaxf(fmaf(acc.x, dv, b4.x), 0.f);
    float r1 = fmaxf(fmaf(acc.y, dv, b4.y), 0.f);
    float r2 = fmaxf(fmaf(acc.z, dv, b4.z), 0.f);
    float r3 = fmaxf(fmaf(acc.w, dv, b4.w), 0.f);
    half4_t o;
    o.a = __floats2half2_rn(r0, r1);
    o.b = __floats2half2_rn(r2, r3);
    ((half4_t*)g_hgcnh)[(size_t)v * 32 + lane] = o;
}

// fused: SAGE mean gather + (neigh @ Wl + h_gcn @ Wr + b) + relu + pool
__global__ void k_gemm2(const float* __restrict__ Wl, const float* __restrict__ Wr,
                        const float* __restrict__ b, const void* __restrict__ batch) {
    __shared__ float ns[8][HID];
    __shared__ float hs[8][HID];
    __shared__ int bg[8];
    int r0 = blockIdx.x * 8;
    int t = threadIdx.x;
    int w = t >> 5, lane = t & 31;
    #pragma unroll
    for (int r = 0; r < 8; r++)
        hs[r][t] = __half2float(g_hgcnh[(size_t)(r0 + r) * HID + t]);
    if (t < 8) bg[t] = idx_at(batch, r0 + t, N_GRAPHS - 1);

    // gather mean(neigh) for 2 nodes per warp
    const half4_t* base = (const half4_t*)g_hgcnh;
    #pragma unroll
    for (int j = 0; j < 2; j++) {
        int r = w * 2 + j;
        int v = r0 + r;
        float4 acc = make_float4(0.f, 0.f, 0.f, 0.f);
        int beg = g_off[v], end = g_off[v + 1];
        int i = beg;
        for (; i + 8 <= end; i += 8) {
            int s0 = g_csr[i],     s1 = g_csr[i + 1], s2 = g_csr[i + 2], s3 = g_csr[i + 3];
            int s4 = g_csr[i + 4], s5 = g_csr[i + 5], s6 = g_csr[i + 6], s7 = g_csr[i + 7];
            half4_t a0 = base[(size_t)s0 * 32 + lane];
            half4_t a1 = base[(size_t)s1 * 32 + lane];
            half4_t a2 = base[(size_t)s2 * 32 + lane];
            half4_t a3 = base[(size_t)s3 * 32 + lane];
            half4_t a4 = base[(size_t)s4 * 32 + lane];
            half4_t a5 = base[(size_t)s5 * 32 + lane];
            half4_t a6 = base[(size_t)s6 * 32 + lane];
            half4_t a7 = base[(size_t)s7 * 32 + lane];
            acc4(acc, a0); acc4(acc, a1); acc4(acc, a2); acc4(acc, a3);
            acc4(acc, a4); acc4(acc, a5); acc4(acc, a6); acc4(acc, a7);
        }
        for (; i < end; i++) acc4(acc, base[(size_t)g_csr[i] * 32 + lane]);
        float inv = 1.f / fmaxf((float)(end - beg), 1.f);
        acc.x *= inv; acc.y *= inv; acc.z *= inv; acc.w *= inv;
        ((float4*)ns[r])[lane] = acc;
    }
    __syncthreads();

    float acc[8];
    float bt = b[t];
    #pragma unroll
    for (int r = 0; r < 8; r++) acc[r] = bt;
    #pragma unroll 4
    for (int k = 0; k < HID; k++) {
        float wl = Wl[k * HID + t];
        float wr = Wr[k * HID + t];
        #pragma unroll
        for (int r = 0; r < 8; r++) {
            acc[r] = fmaf(ns[r][k], wl, acc[r]);
            acc[r] = fmaf(hs[r][k], wr, acc[r]);
        }
    }
    // fused global_add_pool: batch sorted -> run-accumulate, flush on change
    float psum = 0.f;
    int cur = bg[0];
    #pragma unroll
    for (int r = 0; r < 8; r++) {
        int g = bg[r];
        if (g != cur) {
            atomicAdd(&g_pooled[cur * HID + t], psum);
            psum = 0.f; cur = g;
        }
        psum += fmaxf(acc[r], 0.f);
    }
    atomicAdd(&g_pooled[cur * HID + t], psum);
}

// MLP head
__global__ void k_head(const float* __restrict__ Wfc1, const float* __restrict__ b1,
                       const float* __restrict__ Wfc2, const float* __restrict__ b2,
                       float* __restrict__ out) {
    __shared__ float hid[HID];
    int g = blockIdx.x;
    int t = threadIdx.x;
    float acc = b1[t];
    #pragma unroll 8
    for (int k = 0; k < HID; k++)
        acc = fmaf(g_pooled[g * HID + k], Wfc1[k * HID + t], acc);
    hid[t] = fmaxf(acc, 0.f);
    __syncthreads();
    if (t < OUT_DIM) {
        float o = b2[t];
        #pragma unroll 8
        for (int k = 0; k < HID; k++)
            o = fmaf(hid[k], Wfc2[k * OUT_DIM + t], o);
        out[g * OUT_DIM + t] = o;
    }
}

// ---------------- launch ------------------------------------------------------
extern "C" void kernel_launch(void* const* d_in, const int* in_sizes, int n_in,
                              void* d_out, int out_size) {
    int map[12] = {0,1,2,3,4,5,6,7,8,9,10,11};
    if (n_in >= 12 && in_sizes[0] != 2560000) {
        const int alpha[12] = {11, 10,  9,  2,  7,  3,  4,  8,  0,  5,  1,  6};
        for (int i = 0; i < 12; i++) map[i] = alpha[i];
    }
    const float* x      = (const float*)d_in[map[0]];
    const void*  eidx   = d_in[map[1]];
    const void*  batch  = d_in[map[2]];
    const float* W_gcn  = (const float*)d_in[map[3]];
    const float* b_gcn  = (const float*)d_in[map[4]];
    const float* W_sl   = (const float*)d_in[map[5]];
    const float* W_sr   = (const float*)d_in[map[6]];
    const float* b_sage = (const float*)d_in[map[7]];
    const float* W_fc1  = (const float*)d_in[map[8]];
    const float* b_fc1  = (const float*)d_in[map[9]];
    const float* W_fc2  = (const float*)d_in[map[10]];
    const float* b_fc2  = (const float*)d_in[map[11]];
    float* out = (float*)d_out;

    k_init<<<160, 256>>>((const int*)eidx);
    k_count<<<(N_EDGES + 255) / 256, 256>>>(eidx);
    k_blockscan<<<NBLK, 128>>>();
    k_addoff<<<NBLK, 128>>>();
    k_fill<<<(N_EDGES + 255) / 256, 256>>>(eidx);

    k_gemm1<<<N_NODES / 8, HID>>>(x, W_gcn);
    k_gcn_agg<<<(N_NODES * 32 + 255) / 256, 256>>>(b_gcn);
    k_gemm2<<<N_NODES / 8, HID>>>(W_sl, W_sr, b_sage, batch);
    k_head<<<N_GRAPHS, HID>>>(W_fc1, b_fc1, W_fc2, b_fc2, out);
}

// round 7
// speedup vs baseline: 1.7008x; 1.0499x over previous
#include <cuda_runtime.h>
#include <cuda_fp16.h>

#define N_NODES 20000
#define N_EDGES 640000
#define HID     128
#define N_GRAPHS 32
#define OUT_DIM 3
#define NBLK    ((N_NODES + 127) / 128)   // 157 scan blocks

typedef struct { __half2 a, b; } half4_t;   // 8 bytes: 4 half features

// ---------------- scratch (static device globals; no allocation) -------------
__device__ __half g_hh    [N_NODES * HID];  // (x @ W_gcn) * dinv, fp16
__device__ __half g_hgcnh [N_NODES * HID];  // relu(GCN), fp16
__device__ float  g_dinv  [N_NODES];
__device__ int    g_cnt   [N_NODES];
__device__ int    g_off   [N_NODES + 1];
__device__ int    g_csr   [N_EDGES];
__device__ int    g_bsum  [NBLK];
__device__ float  g_pooled[N_GRAPHS * HID];
__device__ int    g_is64;

__device__ __forceinline__ int clampi(int v, int lo, int hi) {
    return v < lo ? lo : (v > hi ? hi : v);
}
__device__ __forceinline__ int idx_at(const void* p, long long i, int hi) {
    int v = g_is64 ? (int)((const long long*)p)[i] : ((const int*)p)[i];
    return clampi(v, 0, hi);
}
__device__ __forceinline__ void acc4(float4& acc, half4_t h) {
    float2 lo = __half22float2(h.a);
    float2 hi = __half22float2(h.b);
    acc.x += lo.x; acc.y += lo.y; acc.z += hi.x; acc.w += hi.y;
}

// ---- packed f32x2 FMA (Blackwell FFMA2; only reachable via PTX) --------------
__device__ __forceinline__ unsigned long long pack2(float lo, float hi) {
    unsigned long long r;
    asm("mov.b64 %0, {%1, %2};" : "=l"(r) : "f"(lo), "f"(hi));
    return r;
}
__device__ __forceinline__ void ffma2(unsigned long long& d,
                                      unsigned long long a, unsigned long long b) {
    asm("fma.rn.f32x2 %0, %1, %2, %0;" : "+l"(d) : "l"(a), "l"(b));
}
__device__ __forceinline__ float2 unpack2(unsigned long long v) {
    float lo, hi;
    asm("mov.b64 {%0, %1}, %2;" : "=f"(lo), "=f"(hi) : "l"(v));
    return make_float2(lo, hi);
}

// ---------------- CSR construction -------------------------------------------

__global__ void k_init(const int* __restrict__ eraw) {
    int i = blockIdx.x * blockDim.x + threadIdx.x;
    if (i == 0) {
        int all_zero = 1;
        #pragma unroll
        for (int j = 0; j < 32; j += 2)
            if (eraw[j + 1] != 0) { all_zero = 0; break; }
        g_is64 = all_zero;
    }
    int stride = gridDim.x * blockDim.x;
    for (int j = i; j < N_NODES; j += stride) g_cnt[j] = 0;
    for (int j = i; j < N_GRAPHS * HID; j += stride) g_pooled[j] = 0.f;
}

__global__ void k_count(const void* __restrict__ eidx) {
    int e = blockIdx.x * blockDim.x + threadIdx.x;
    if (e < N_EDGES) {
        int c = idx_at(eidx, (long long)N_EDGES + e, N_NODES - 1);
        atomicAdd(&g_cnt[c], 1);
    }
}

// per-block exclusive scan via warp shuffles; also computes dinv (fused)
__global__ void k_blockscan() {
    int t = threadIdx.x;
    int i = blockIdx.x * 128 + t;
    int v = (i < N_NODES) ? g_cnt[i] : 0;
    int lane = t & 31, w = t >> 5;
    int inc = v;
    #pragma unroll
    for (int s = 1; s < 32; s <<= 1) {
        int n = __shfl_up_sync(0xffffffffu, inc, s);
        if (lane >= s) inc += n;
    }
    __shared__ int wsum[4];
    if (lane == 31) wsum[w] = inc;
    __syncthreads();
    int woff = 0;
    #pragma unroll
    for (int j = 0; j < 4; j++) if (j < w) woff += wsum[j];
    if (i < N_NODES) {
        g_off[i] = woff + inc - v;
        g_dinv[i] = rsqrtf((float)(v + 1));   // +1 self loop
    }
    if (t == 127) g_bsum[blockIdx.x] = woff + inc;
}

// add block offset (reduce own prefix of block sums inline)
__global__ void k_addoff() {
    __shared__ int red[4];
    __shared__ int boff;
    int t = threadIdx.x;
    int bid = blockIdx.x;
    int partial = 0;
    for (int j = t; j < bid; j += 128) partial += g_bsum[j];
    int lane = t & 31, w = t >> 5;
    #pragma unroll
    for (int s = 16; s > 0; s >>= 1)
        partial += __shfl_down_sync(0xffffffffu, partial, s);
    if (lane == 0) red[w] = partial;
    __syncthreads();
    if (t == 0) boff = red[0] + red[1] + red[2] + red[3];
    __syncthreads();
    int i = bid * 128 + t;
    if (i < N_NODES) g_off[i] += boff;
    if (i == 0) g_off[N_NODES] = N_EDGES;
}

// fill CSR, consuming g_cnt as the per-node cursor (counts down)
__global__ void k_fill(const void* __restrict__ eidx) {
    int e = blockIdx.x * blockDim.x + threadIdx.x;
    if (e < N_EDGES) {
        int r = idx_at(eidx, e, N_NODES - 1);
        int c = idx_at(eidx, (long long)N_EDGES + e, N_NODES - 1);
        int pos = g_off[c] + atomicAdd(&g_cnt[c], -1) - 1;
        if (pos >= 0 && pos < N_EDGES) g_csr[pos] = r;
    }
}

// ---------------- compute -----------------------------------------------------

// g_hh = half((X @ W) * dinv) — 8 rows/block, FFMA2 path, k-major smem tile
__global__ void k_gemm1(const float* __restrict__ X, const float* __restrict__ W) {
    __shared__ __align__(16) float xs[HID][12];   // [k][row], 48B rows (16B-aligned)
    __shared__ float dv[8];
    int r0 = blockIdx.x * 8;
    int t = threadIdx.x;
    #pragma unroll
    for (int r = 0; r < 8; r++) xs[t][r] = X[(size_t)(r0 + r) * HID + t];
    if (t < 8) dv[t] = g_dinv[r0 + t];
    __syncthreads();
    unsigned long long acc[4] = {0ull, 0ull, 0ull, 0ull};   // rows (0,1)..(6,7)
    #pragma unroll 4
    for (int k = 0; k < HID; k++) {
        float w = W[k * HID + t];
        unsigned long long wp = pack2(w, w);
        const ulonglong2* p = (const ulonglong2*)&xs[k][0];  // LDS.128 broadcast
        ulonglong2 x01 = p[0];
        ulonglong2 x23 = p[1];
        ffma2(acc[0], x01.x, wp);
        ffma2(acc[1], x01.y, wp);
        ffma2(acc[2], x23.x, wp);
        ffma2(acc[3], x23.y, wp);
    }
    #pragma unroll
    for (int q = 0; q < 4; q++) {
        float2 v = unpack2(acc[q]);
        g_hh[(size_t)(r0 + 2 * q)     * HID + t] = __float2half_rn(v.x * dv[2 * q]);
        g_hh[(size_t)(r0 + 2 * q + 1) * HID + t] = __float2half_rn(v.y * dv[2 * q + 1]);
    }
}

// GCN gather (fp16 rows, fp32 accum, 8-deep MLP)
__global__ void k_gcn_agg(const float* __restrict__ b_gcn) {
    int warp = (blockIdx.x * blockDim.x + threadIdx.x) >> 5;
    int lane = threadIdx.x & 31;
    if (warp >= N_NODES) return;
    int v = warp;
    float dv = g_dinv[v];
    const half4_t* base = (const half4_t*)g_hh;
    float4 acc = make_float4(0.f, 0.f, 0.f, 0.f);
    acc4(acc, base[(size_t)v * 32 + lane]);         // self term
    int beg = g_off[v], end = g_off[v + 1];
    int i = beg;
    for (; i + 8 <= end; i += 8) {
        int s0 = g_csr[i],     s1 = g_csr[i + 1], s2 = g_csr[i + 2], s3 = g_csr[i + 3];
        int s4 = g_csr[i + 4], s5 = g_csr[i + 5], s6 = g_csr[i + 6], s7 = g_csr[i + 7];
        half4_t a = base[(size_t)s0 * 32 + lane];
        half4_t b = base[(size_t)s1 * 32 + lane];
        half4_t c = base[(size_t)s2 * 32 + lane];
        half4_t d = base[(size_t)s3 * 32 + lane];
        half4_t e = base[(size_t)s4 * 32 + lane];
        half4_t f = base[(size_t)s5 * 32 + lane];
        half4_t g = base[(size_t)s6 * 32 + lane];
        half4_t h = base[(size_t)s7 * 32 + lane];
        acc4(acc, a); acc4(acc, b); acc4(acc, c); acc4(acc, d);
        acc4(acc, e); acc4(acc, f); acc4(acc, g); acc4(acc, h);
    }
    for (; i < end; i++) acc4(acc, base[(size_t)g_csr[i] * 32 + lane]);
    float4 b4 = ((const float4*)b_gcn)[lane];
    float r0 = fmaxf(fmaf(acc.x, dv, b4.x), 0.f);
    float r1 = fmaxf(fmaf(acc.y, dv, b4.y), 0.f);
    float r2 = fmaxf(fmaf(acc.z, dv, b4.z), 0.f);
    float r3 = fmaxf(fmaf(acc.w, dv, b4.w), 0.f);
    half4_t o;
    o.a = __floats2half2_rn(r0, r1);
    o.b = __floats2half2_rn(r2, r3);
    ((half4_t*)g_hgcnh)[(size_t)v * 32 + lane] = o;
}

// fused: SAGE mean gather + FFMA2 dual-GEMM + relu + pool
__global__ void k_gemm2(const float* __restrict__ Wl, const float* __restrict__ Wr,
                        const float* __restrict__ b, const void* __restrict__ batch) {
    __shared__ __align__(16) float nsp[HID][12];  // [k][row]
    __shared__ __align__(16) float hsp[HID][12];  // [k][row]
    __shared__ float ns[8][HID];                  // gather staging (row-major)
    __shared__ int bg[8];
    int r0 = blockIdx.x * 8;
    int t = threadIdx.x;
    int w = t >> 5, lane = t & 31;
    #pragma unroll
    for (int r = 0; r < 8; r++)
        hsp[t][r] = __half2float(g_hgcnh[(size_t)(r0 + r) * HID + t]);
    if (t < 8) bg[t] = idx_at(batch, r0 + t, N_GRAPHS - 1);

    // gather mean(neigh) for 2 nodes per warp (row-major staging)
    const half4_t* base = (const half4_t*)g_hgcnh;
    #pragma unroll
    for (int j = 0; j < 2; j++) {
        int r = w * 2 + j;
        int v = r0 + r;
        float4 acc = make_float4(0.f, 0.f, 0.f, 0.f);
        int beg = g_off[v], end = g_off[v + 1];
        int i = beg;
        for (; i + 8 <= end; i += 8) {
            int s0 = g_csr[i],     s1 = g_csr[i + 1], s2 = g_csr[i + 2], s3 = g_csr[i + 3];
            int s4 = g_csr[i + 4], s5 = g_csr[i + 5], s6 = g_csr[i + 6], s7 = g_csr[i + 7];
            half4_t a0 = base[(size_t)s0 * 32 + lane];
            half4_t a1 = base[(size_t)s1 * 32 + lane];
            half4_t a2 = base[(size_t)s2 * 32 + lane];
            half4_t a3 = base[(size_t)s3 * 32 + lane];
            half4_t a4 = base[(size_t)s4 * 32 + lane];
            half4_t a5 = base[(size_t)s5 * 32 + lane];
            half4_t a6 = base[(size_t)s6 * 32 + lane];
            half4_t a7 = base[(size_t)s7 * 32 + lane];
            acc4(acc, a0); acc4(acc, a1); acc4(acc, a2); acc4(acc, a3);
            acc4(acc, a4); acc4(acc, a5); acc4(acc, a6); acc4(acc, a7);
        }
        for (; i < end; i++) acc4(acc, base[(size_t)g_csr[i] * 32 + lane]);
        float inv = 1.f / fmaxf((float)(end - beg), 1.f);
        acc.x *= inv; acc.y *= inv; acc.z *= inv; acc.w *= inv;
        ((float4*)ns[r])[lane] = acc;
    }
    __syncthreads();
    // transpose gather staging into k-major for vector LDS
    #pragma unroll
    for (int r = 0; r < 8; r++) nsp[t][r] = ns[r][t];
    __syncthreads();

    float bt = b[t];
    unsigned long long acc[4];
    #pragma unroll
    for (int q = 0; q < 4; q++) acc[q] = pack2(bt, bt);
    #pragma unroll 4
    for (int k = 0; k < HID; k++) {
        unsigned long long wlp, wrp;
        {
            float wl = Wl[k * HID + t];
            float wr = Wr[k * HID + t];
            wlp = pack2(wl, wl);
            wrp = pack2(wr, wr);
        }
        const ulonglong2* pn = (const ulonglong2*)&nsp[k][0];
        const ulonglong2* ph = (const ulonglong2*)&hsp[k][0];
        ulonglong2 n01 = pn[0], n23 = pn[1];
        ulonglong2 h01 = ph[0], h23 = ph[1];
        ffma2(acc[0], n01.x, wlp); ffma2(acc[0], h01.x, wrp);
        ffma2(acc[1], n01.y, wlp); ffma2(acc[1], h01.y, wrp);
        ffma2(acc[2], n23.x, wlp); ffma2(acc[2], h23.x, wrp);
        ffma2(acc[3], n23.y, wlp); ffma2(acc[3], h23.y, wrp);
    }
    // fused global_add_pool: batch sorted -> run-accumulate, flush on change
    float psum = 0.f;
    int cur = bg[0];
    #pragma unroll
    for (int q = 0; q < 4; q++) {
        float2 v = unpack2(acc[q]);
        int g0 = bg[2 * q], g1 = bg[2 * q + 1];
        if (g0 != cur) { atomicAdd(&g_pooled[cur * HID + t], psum); psum = 0.f; cur = g0; }
        psum += fmaxf(v.x, 0.f);
        if (g1 != cur) { atomicAdd(&g_pooled[cur * HID + t], psum); psum = 0.f; cur = g1; }
        psum += fmaxf(v.y, 0.f);
    }
    atomicAdd(&g_pooled[cur * HID + t], psum);
}

// MLP head
__global__ void k_head(const float* __restrict__ Wfc1, const float* __restrict__ b1,
                       const float* __restrict__ Wfc2, const float* __restrict__ b2,
                       float* __restrict__ out) {
    __shared__ float hid[HID];
    int g = blockIdx.x;
    int t = threadIdx.x;
    float acc = b1[t];
    #pragma unroll 8
    for (int k = 0; k < HID; k++)
        acc = fmaf(g_pooled[g * HID + k], Wfc1[k * HID + t], acc);
    hid[t] = fmaxf(acc, 0.f);
    __syncthreads();
    if (t < OUT_DIM) {
        float o = b2[t];
        #pragma unroll 8
        for (int k = 0; k < HID; k++)
            o = fmaf(hid[k], Wfc2[k * OUT_DIM + t], o);
        out[g * OUT_DIM + t] = o;
    }
}

// ---------------- launch ------------------------------------------------------
extern "C" void kernel_launch(void* const* d_in, const int* in_sizes, int n_in,
                              void* d_out, int out_size) {
    int map[12] = {0,1,2,3,4,5,6,7,8,9,10,11};
    if (n_in >= 12 && in_sizes[0] != 2560000) {
        const int alpha[12] = {11, 10,  9,  2,  7,  3,  4,  8,  0,  5,  1,  6};
        for (int i = 0; i < 12; i++) map[i] = alpha[i];
    }
    const float* x      = (const float*)d_in[map[0]];
    const void*  eidx   = d_in[map[1]];
    const void*  batch  = d_in[map[2]];
    const float* W_gcn  = (const float*)d_in[map[3]];
    const float* b_gcn  = (const float*)d_in[map[4]];
    const float* W_sl   = (const float*)d_in[map[5]];
    const float* W_sr   = (const float*)d_in[map[6]];
    const float* b_sage = (const float*)d_in[map[7]];
    const float* W_fc1  = (const float*)d_in[map[8]];
    const float* b_fc1  = (const float*)d_in[map[9]];
    const float* W_fc2  = (const float*)d_in[map[10]];
    const float* b_fc2  = (const float*)d_in[map[11]];
    float* out = (float*)d_out;

    k_init<<<160, 256>>>((const int*)eidx);                 // 1
    k_count<<<(N_EDGES + 255) / 256, 256>>>(eidx);          // 2
    k_blockscan<<<NBLK, 128>>>();                           // 3 (also dinv)
    k_gemm1<<<N_NODES / 8, HID>>>(x, W_gcn);                // 4 <- profiled slot
    k_addoff<<<NBLK, 128>>>();                              // 5
    k_fill<<<(N_EDGES + 255) / 256, 256>>>(eidx);           // 6
    k_gcn_agg<<<(N_NODES * 32 + 255) / 256, 256>>>(b_gcn);  // 7
    k_gemm2<<<N_NODES / 8, HID>>>(W_sl, W_sr, b_sage, batch);// 8
    k_head<<<N_GRAPHS, HID>>>(W_fc1, b_fc1, W_fc2, b_fc2, out);
}

// round 8
// speedup vs baseline: 1.7152x; 1.0085x over previous
#include <cuda_runtime.h>
#include <cuda_fp16.h>
#include <mma.h>
using namespace nvcuda;

#define N_NODES 20000
#define N_EDGES 640000
#define HID     128
#define N_GRAPHS 32
#define OUT_DIM 3
#define NBLK    ((N_NODES + 127) / 128)   // 157 scan blocks

typedef struct { __half2 a, b; } half4_t;   // 8 bytes: 4 half features

// ---------------- scratch (static device globals; no allocation) -------------
__device__ __half g_hh    [N_NODES * HID];  // (x @ W_gcn) * dinv, fp16
__device__ __half g_hgcnh [N_NODES * HID];  // relu(GCN), fp16
__device__ float  g_dinv  [N_NODES];
__device__ int    g_cnt   [N_NODES];
__device__ int    g_off   [N_NODES + 1];
__device__ int    g_csr   [N_EDGES];
__device__ int    g_bsum  [NBLK];
__device__ float  g_pooled[N_GRAPHS * HID];
__device__ int    g_is64;

__device__ __forceinline__ int clampi(int v, int lo, int hi) {
    return v < lo ? lo : (v > hi ? hi : v);
}
__device__ __forceinline__ int idx_at(const void* p, long long i, int hi) {
    int v = g_is64 ? (int)((const long long*)p)[i] : ((const int*)p)[i];
    return clampi(v, 0, hi);
}
__device__ __forceinline__ void acc4(float4& acc, half4_t h) {
    float2 lo = __half22float2(h.a);
    float2 hi = __half22float2(h.b);
    acc.x += lo.x; acc.y += lo.y; acc.z += hi.x; acc.w += hi.y;
}

// ---------------- CSR construction -------------------------------------------

__global__ void k_init(const int* __restrict__ eraw) {
    int i = blockIdx.x * blockDim.x + threadIdx.x;
    if (i == 0) {
        int all_zero = 1;
        #pragma unroll
        for (int j = 0; j < 32; j += 2)
            if (eraw[j + 1] != 0) { all_zero = 0; break; }
        g_is64 = all_zero;
    }
    int stride = gridDim.x * blockDim.x;
    for (int j = i; j < N_NODES; j += stride) g_cnt[j] = 0;
    for (int j = i; j < N_GRAPHS * HID; j += stride) g_pooled[j] = 0.f;
}

__global__ void k_count(const void* __restrict__ eidx) {
    int e = blockIdx.x * blockDim.x + threadIdx.x;
    if (e < N_EDGES) {
        int c = idx_at(eidx, (long long)N_EDGES + e, N_NODES - 1);
        atomicAdd(&g_cnt[c], 1);
    }
}

// per-block exclusive scan via warp shuffles; also computes dinv (fused)
__global__ void k_blockscan() {
    int t = threadIdx.x;
    int i = blockIdx.x * 128 + t;
    int v = (i < N_NODES) ? g_cnt[i] : 0;
    int lane = t & 31, w = t >> 5;
    int inc = v;
    #pragma unroll
    for (int s = 1; s < 32; s <<= 1) {
        int n = __shfl_up_sync(0xffffffffu, inc, s);
        if (lane >= s) inc += n;
    }
    __shared__ int wsum[4];
    if (lane == 31) wsum[w] = inc;
    __syncthreads();
    int woff = 0;
    #pragma unroll
    for (int j = 0; j < 4; j++) if (j < w) woff += wsum[j];
    if (i < N_NODES) {
        g_off[i] = woff + inc - v;
        g_dinv[i] = rsqrtf((float)(v + 1));   // +1 self loop
    }
    if (t == 127) g_bsum[blockIdx.x] = woff + inc;
}

// add block offset (reduce own prefix of block sums inline)
__global__ void k_addoff() {
    __shared__ int red[4];
    __shared__ int boff;
    int t = threadIdx.x;
    int bid = blockIdx.x;
    int partial = 0;
    for (int j = t; j < bid; j += 128) partial += g_bsum[j];
    int lane = t & 31, w = t >> 5;
    #pragma unroll
    for (int s = 16; s > 0; s >>= 1)
        partial += __shfl_down_sync(0xffffffffu, partial, s);
    if (lane == 0) red[w] = partial;
    __syncthreads();
    if (t == 0) boff = red[0] + red[1] + red[2] + red[3];
    __syncthreads();
    int i = bid * 128 + t;
    if (i < N_NODES) g_off[i] += boff;
    if (i == 0) g_off[N_NODES] = N_EDGES;
}

// fill CSR, consuming g_cnt as the per-node cursor (counts down)
__global__ void k_fill(const void* __restrict__ eidx) {
    int e = blockIdx.x * blockDim.x + threadIdx.x;
    if (e < N_EDGES) {
        int r = idx_at(eidx, e, N_NODES - 1);
        int c = idx_at(eidx, (long long)N_EDGES + e, N_NODES - 1);
        int pos = g_off[c] + atomicAdd(&g_cnt[c], -1) - 1;
        if (pos >= 0 && pos < N_EDGES) g_csr[pos] = r;
    }
}

// ---------------- compute -----------------------------------------------------

// g_hh = half((X @ W) * dinv) — wmma, 32 rows/block, 256 threads (8 warps)
__global__ void __launch_bounds__(256) k_gemm1(const float* __restrict__ X,
                                               const float* __restrict__ W) {
    __shared__ __align__(32) __half xa[32][HID];   // 8KB  A tile (fp16)
    __shared__ __align__(32) __half wb[32][HID];   // 8KB  W k-chunk (fp16)
    __shared__ float outb[32][HID];                // 16KB epilogue
    __shared__ float dv[32];
    int r0 = blockIdx.x * 32;
    int tid = threadIdx.x;
    int warp = tid >> 5;
    #pragma unroll
    for (int i = 0; i < 16; i++) {
        int idx = tid + i * 256;
        int r = idx >> 7, c = idx & 127;
        xa[r][c] = __float2half_rn(X[(size_t)(r0 + r) * HID + c]);
    }
    if (tid < 32) dv[tid] = g_dinv[r0 + tid];

    wmma::fragment<wmma::accumulator, 16, 16, 16, float> cf[2];
    wmma::fill_fragment(cf[0], 0.f);
    wmma::fill_fragment(cf[1], 0.f);
    int n0 = warp * 16;
    for (int kc = 0; kc < 4; kc++) {
        __syncthreads();     // xa ready (kc=0) / wb reuse safe (kc>0)
        #pragma unroll
        for (int i = 0; i < 16; i++) {
            int idx = tid + i * 256;
            int r = idx >> 7, c = idx & 127;
            wb[r][c] = __float2half_rn(W[(size_t)(kc * 32 + r) * HID + c]);
        }
        __syncthreads();
        #pragma unroll
        for (int kt = 0; kt < 2; kt++) {
            wmma::fragment<wmma::matrix_a, 16, 16, 16, __half, wmma::row_major> af;
            wmma::fragment<wmma::matrix_b, 16, 16, 16, __half, wmma::row_major> bf;
            wmma::load_matrix_sync(bf, &wb[kt * 16][n0], HID);
            wmma::load_matrix_sync(af, &xa[0][kc * 32 + kt * 16], HID);
            wmma::mma_sync(cf[0], af, bf, cf[0]);
            wmma::load_matrix_sync(af, &xa[16][kc * 32 + kt * 16], HID);
            wmma::mma_sync(cf[1], af, bf, cf[1]);
        }
    }
    __syncthreads();
    wmma::store_matrix_sync(&outb[0][n0], cf[0], HID, wmma::mem_row_major);
    wmma::store_matrix_sync(&outb[16][n0], cf[1], HID, wmma::mem_row_major);
    __syncthreads();
    #pragma unroll
    for (int i = 0; i < 16; i++) {
        int idx = tid + i * 256;
        int r = idx >> 7, c = idx & 127;
        g_hh[(size_t)(r0 + r) * HID + c] = __float2half_rn(outb[r][c] * dv[r]);
    }
}

// GCN gather (fp16 rows, fp32 accum, 8-deep MLP)
__global__ void k_gcn_agg(const float* __restrict__ b_gcn) {
    int warp = (blockIdx.x * blockDim.x + threadIdx.x) >> 5;
    int lane = threadIdx.x & 31;
    if (warp >= N_NODES) return;
    int v = warp;
    float dv = g_dinv[v];
    const half4_t* base = (const half4_t*)g_hh;
    float4 acc = make_float4(0.f, 0.f, 0.f, 0.f);
    acc4(acc, base[(size_t)v * 32 + lane]);
    int beg = g_off[v], end = g_off[v + 1];
    int i = beg;
    for (; i + 8 <= end; i += 8) {
        int s0 = g_csr[i],     s1 = g_csr[i + 1], s2 = g_csr[i + 2], s3 = g_csr[i + 3];
        int s4 = g_csr[i + 4], s5 = g_csr[i + 5], s6 = g_csr[i + 6], s7 = g_csr[i + 7];
        half4_t a = base[(size_t)s0 * 32 + lane];
        half4_t b = base[(size_t)s1 * 32 + lane];
        half4_t c = base[(size_t)s2 * 32 + lane];
        half4_t d = base[(size_t)s3 * 32 + lane];
        half4_t e = base[(size_t)s4 * 32 + lane];
        half4_t f = base[(size_t)s5 * 32 + lane];
        half4_t g = base[(size_t)s6 * 32 + lane];
        half4_t h = base[(size_t)s7 * 32 + lane];
        acc4(acc, a); acc4(acc, b); acc4(acc, c); acc4(acc, d);
        acc4(acc, e); acc4(acc, f); acc4(acc, g); acc4(acc, h);
    }
    for (; i < end; i++) acc4(acc, base[(size_t)g_csr[i] * 32 + lane]);
    float4 b4 = ((const float4*)b_gcn)[lane];
    float r0 = fmaxf(fmaf(acc.x, dv, b4.x), 0.f);
    float r1 = fmaxf(fmaf(acc.y, dv, b4.y), 0.f);
    float r2 = fmaxf(fmaf(acc.z, dv, b4.z), 0.f);
    float r3 = fmaxf(fmaf(acc.w, dv, b4.w), 0.f);
    half4_t o;
    o.a = __floats2half2_rn(r0, r1);
    o.b = __floats2half2_rn(r2, r3);
    ((half4_t*)g_hgcnh)[(size_t)v * 32 + lane] = o;
}

// fused: SAGE mean gather + wmma dual-GEMM + bias + relu + pool
// 32 rows/block, 256 threads (8 warps)
__global__ void __launch_bounds__(256) k_gemm2(const float* __restrict__ Wl,
                                               const float* __restrict__ Wr,
                                               const float* __restrict__ b,
                                               const void* __restrict__ batch) {
    __shared__ __align__(32) __half hsa[32][HID];  // 8KB
    __shared__ __align__(32) __half nsa[32][HID];  // 8KB
    __shared__ __align__(32) __half wlb[16][HID];  // 4KB (k-chunk)
    __shared__ __align__(32) __half wrb[16][HID];  // 4KB (k-chunk)
    __shared__ float outb[32][HID];                // 16KB
    __shared__ int bg[32];
    int r0 = blockIdx.x * 32;
    int tid = threadIdx.x;
    int warp = tid >> 5, lane = tid & 31;

    // copy h_gcn tile (already fp16): 32 rows x 256B = 512 uint4
    {
        const uint4* src = (const uint4*)(g_hgcnh + (size_t)r0 * HID);
        uint4* dst = (uint4*)&hsa[0][0];
        dst[tid] = src[tid];
        dst[tid + 256] = src[tid + 256];
    }
    if (tid < 32) bg[tid] = idx_at(batch, r0 + tid, N_GRAPHS - 1);

    // gather mean(neigh) for 4 nodes per warp
    const half4_t* base = (const half4_t*)g_hgcnh;
    #pragma unroll
    for (int j = 0; j < 4; j++) {
        int r = warp * 4 + j;
        int v = r0 + r;
        float4 acc = make_float4(0.f, 0.f, 0.f, 0.f);
        int beg = g_off[v], end = g_off[v + 1];
        int i = beg;
        for (; i + 8 <= end; i += 8) {
            int s0 = g_csr[i],     s1 = g_csr[i + 1], s2 = g_csr[i + 2], s3 = g_csr[i + 3];
            int s4 = g_csr[i + 4], s5 = g_csr[i + 5], s6 = g_csr[i + 6], s7 = g_csr[i + 7];
            half4_t a0 = base[(size_t)s0 * 32 + lane];
            half4_t a1 = base[(size_t)s1 * 32 + lane];
            half4_t a2 = base[(size_t)s2 * 32 + lane];
            half4_t a3 = base[(size_t)s3 * 32 + lane];
            half4_t a4 = base[(size_t)s4 * 32 + lane];
            half4_t a5 = base[(size_t)s5 * 32 + lane];
            half4_t a6 = base[(size_t)s6 * 32 + lane];
            half4_t a7 = base[(size_t)s7 * 32 + lane];
            acc4(acc, a0); acc4(acc, a1); acc4(acc, a2); acc4(acc, a3);
            acc4(acc, a4); acc4(acc, a5); acc4(acc, a6); acc4(acc, a7);
        }
        for (; i < end; i++) acc4(acc, base[(size_t)g_csr[i] * 32 + lane]);
        float inv = 1.f / fmaxf((float)(end - beg), 1.f);
        half4_t o;
        o.a = __floats2half2_rn(acc.x * inv, acc.y * inv);
        o.b = __floats2half2_rn(acc.z * inv, acc.w * inv);
        ((half4_t*)&nsa[r][0])[lane] = o;
    }

    wmma::fragment<wmma::accumulator, 16, 16, 16, float> cf[2];
    wmma::fill_fragment(cf[0], 0.f);
    wmma::fill_fragment(cf[1], 0.f);
    int n0 = warp * 16;
    for (int kc = 0; kc < 8; kc++) {
        __syncthreads();     // tiles ready (kc=0) / w chunk reuse safe (kc>0)
        #pragma unroll
        for (int i = 0; i < 8; i++) {
            int idx = tid + i * 256;
            int r = idx >> 7, c = idx & 127;
            wlb[r][c] = __float2half_rn(Wl[(size_t)(kc * 16 + r) * HID + c]);
            wrb[r][c] = __float2half_rn(Wr[(size_t)(kc * 16 + r) * HID + c]);
        }
        __syncthreads();
        wmma::fragment<wmma::matrix_a, 16, 16, 16, __half, wmma::row_major> af;
        wmma::fragment<wmma::matrix_b, 16, 16, 16, __half, wmma::row_major> bl, br;
        wmma::load_matrix_sync(bl, &wlb[0][n0], HID);
        wmma::load_matrix_sync(br, &wrb[0][n0], HID);
        wmma::load_matrix_sync(af, &nsa[0][kc * 16], HID);
        wmma::mma_sync(cf[0], af, bl, cf[0]);
        wmma::load_matrix_sync(af, &hsa[0][kc * 16], HID);
        wmma::mma_sync(cf[0], af, br, cf[0]);
        wmma::load_matrix_sync(af, &nsa[16][kc * 16], HID);
        wmma::mma_sync(cf[1], af, bl, cf[1]);
        wmma::load_matrix_sync(af, &hsa[16][kc * 16], HID);
        wmma::mma_sync(cf[1], af, br, cf[1]);
    }
    __syncthreads();
    wmma::store_matrix_sync(&outb[0][n0], cf[0], HID, wmma::mem_row_major);
    wmma::store_matrix_sync(&outb[16][n0], cf[1], HID, wmma::mem_row_major);
    __syncthreads();

    // epilogue: bias + relu + fused pool (batch sorted -> run accumulate)
    int col = tid & 127, rh = tid >> 7;       // 2 threads/col, 16 rows each
    float bt = b[col];
    float psum = 0.f;
    int cur = bg[rh * 16];
    #pragma unroll
    for (int r = rh * 16; r < rh * 16 + 16; r++) {
        int g = bg[r];
        if (g != cur) {
            atomicAdd(&g_pooled[cur * HID + col], psum);
            psum = 0.f; cur = g;
        }
        psum += fmaxf(outb[r][col] + bt, 0.f);
    }
    atomicAdd(&g_pooled[cur * HID + col], psum);
}

// MLP head
__global__ void k_head(const float* __restrict__ Wfc1, const float* __restrict__ b1,
                       const float* __restrict__ Wfc2, const float* __restrict__ b2,
                       float* __restrict__ out) {
    __shared__ float hid[HID];
    int g = blockIdx.x;
    int t = threadIdx.x;
    float acc = b1[t];
    #pragma unroll 8
    for (int k = 0; k < HID; k++)
        acc = fmaf(g_pooled[g * HID + k], Wfc1[k * HID + t], acc);
    hid[t] = fmaxf(acc, 0.f);
    __syncthreads();
    if (t < OUT_DIM) {
        float o = b2[t];
        #pragma unroll 8
        for (int k = 0; k < HID; k++)
            o = fmaf(hid[k], Wfc2[k * OUT_DIM + t], o);
        out[g * OUT_DIM + t] = o;
    }
}

// ---------------- launch ------------------------------------------------------
extern "C" void kernel_launch(void* const* d_in, const int* in_sizes, int n_in,
                              void* d_out, int out_size) {
    int map[12] = {0,1,2,3,4,5,6,7,8,9,10,11};
    if (n_in >= 12 && in_sizes[0] != 2560000) {
        const int alpha[12] = {11, 10,  9,  2,  7,  3,  4,  8,  0,  5,  1,  6};
        for (int i = 0; i < 12; i++) map[i] = alpha[i];
    }
    const float* x      = (const float*)d_in[map[0]];
    const void*  eidx   = d_in[map[1]];
    const void*  batch  = d_in[map[2]];
    const float* W_gcn  = (const float*)d_in[map[3]];
    const float* b_gcn  = (const float*)d_in[map[4]];
    const float* W_sl   = (const float*)d_in[map[5]];
    const float* W_sr   = (const float*)d_in[map[6]];
    const float* b_sage = (const float*)d_in[map[7]];
    const float* W_fc1  = (const float*)d_in[map[8]];
    const float* b_fc1  = (const float*)d_in[map[9]];
    const float* W_fc2  = (const float*)d_in[map[10]];
    const float* b_fc2  = (const float*)d_in[map[11]];
    float* out = (float*)d_out;

    k_init<<<160, 256>>>((const int*)eidx);                 // 1
    k_count<<<(N_EDGES + 255) / 256, 256>>>(eidx);          // 2
    k_blockscan<<<NBLK, 128>>>();                           // 3 (also dinv)
    k_gemm1<<<N_NODES / 32, 256>>>(x, W_gcn);               // 4 <- profiled slot
    k_addoff<<<NBLK, 128>>>();                              // 5
    k_fill<<<(N_EDGES + 255) / 256, 256>>>(eidx);           // 6
    k_gcn_agg<<<(N_NODES * 32 + 255) / 256, 256>>>(b_gcn);  // 7
    k_gemm2<<<N_NODES / 32, 256>>>(W_sl, W_sr, b_sage, batch); // 8
    k_head<<<N_GRAPHS, HID>>>(W_fc1, b_fc1, W_fc2, b_fc2, out);
}

// round 9
// speedup vs baseline: 1.7439x; 1.0167x over previous
#include <cuda_runtime.h>
#include <cuda_fp16.h>
#include <mma.h>
using namespace nvcuda;

#define N_NODES 20000
#define N_EDGES 640000
#define HID     128
#define N_GRAPHS 32
#define OUT_DIM 3
#define NBLK    ((N_NODES + 127) / 128)    // 157 scan blocks
#define GROWS   64                          // rows per GEMM block
#define GRID_G  ((N_NODES + GROWS - 1) / GROWS)   // 313
#define N_PAD   (GRID_G * GROWS)            // 20032 (padded rows)

typedef struct { __half2 a, b; } half4_t;   // 8 bytes: 4 half features

// ---------------- scratch (static device globals; no allocation) -------------
__device__ __half g_hh    [N_PAD * HID];    // (x*dinv) @ W_gcn, fp16
__device__ __half g_hgcnh [N_PAD * HID];    // relu(GCN), fp16
__device__ __half g_wgcn16[HID * HID];      // fp16 weights (pre-converted)
__device__ __half g_wl16  [HID * HID];
__device__ __half g_wr16  [HID * HID];
__device__ float  g_dinv  [N_NODES];
__device__ int    g_cnt   [N_NODES];
__device__ int    g_off   [N_NODES + 1];
__device__ int    g_csr   [N_EDGES];
__device__ int    g_bsum  [NBLK];
__device__ float  g_pooled[N_GRAPHS * HID];
__device__ int    g_is64;

__device__ __forceinline__ int clampi(int v, int lo, int hi) {
    return v < lo ? lo : (v > hi ? hi : v);
}
__device__ __forceinline__ int idx_at(const void* p, long long i, int hi) {
    int v = g_is64 ? (int)((const long long*)p)[i] : ((const int*)p)[i];
    return clampi(v, 0, hi);
}
__device__ __forceinline__ void acc4(float4& acc, half4_t h) {
    float2 lo = __half22float2(h.a);
    float2 hi = __half22float2(h.b);
    acc.x += lo.x; acc.y += lo.y; acc.z += hi.x; acc.w += hi.y;
}

// ---------------- CSR construction + init ------------------------------------

// detect dtype, zero counters/pool, pre-convert weights to fp16 (all fused)
__global__ void k_init(const int* __restrict__ eraw,
                       const float* __restrict__ Wg,
                       const float* __restrict__ Wl,
                       const float* __restrict__ Wr) {
    int i = blockIdx.x * blockDim.x + threadIdx.x;
    int stride = gridDim.x * blockDim.x;
    if (i == 0) {
        int all_zero = 1;
        #pragma unroll
        for (int j = 0; j < 32; j += 2)
            if (eraw[j + 1] != 0) { all_zero = 0; break; }
        g_is64 = all_zero;
    }
    for (int j = i; j < N_NODES; j += stride) g_cnt[j] = 0;
    for (int j = i; j < N_GRAPHS * HID; j += stride) g_pooled[j] = 0.f;
    for (int j = i; j < HID * HID; j += stride) {
        g_wgcn16[j] = __float2half_rn(Wg[j]);
        g_wl16[j]   = __float2half_rn(Wl[j]);
        g_wr16[j]   = __float2half_rn(Wr[j]);
    }
}

__global__ void k_count(const void* __restrict__ eidx) {
    int e = blockIdx.x * blockDim.x + threadIdx.x;
    if (e < N_EDGES) {
        int c = idx_at(eidx, (long long)N_EDGES + e, N_NODES - 1);
        atomicAdd(&g_cnt[c], 1);
    }
}

// per-block exclusive scan via warp shuffles; also computes dinv (fused)
__global__ void k_blockscan() {
    int t = threadIdx.x;
    int i = blockIdx.x * 128 + t;
    int v = (i < N_NODES) ? g_cnt[i] : 0;
    int lane = t & 31, w = t >> 5;
    int inc = v;
    #pragma unroll
    for (int s = 1; s < 32; s <<= 1) {
        int n = __shfl_up_sync(0xffffffffu, inc, s);
        if (lane >= s) inc += n;
    }
    __shared__ int wsum[4];
    if (lane == 31) wsum[w] = inc;
    __syncthreads();
    int woff = 0;
    #pragma unroll
    for (int j = 0; j < 4; j++) if (j < w) woff += wsum[j];
    if (i < N_NODES) {
        g_off[i] = woff + inc - v;
        g_dinv[i] = rsqrtf((float)(v + 1));   // +1 self loop
    }
    if (t == 127) g_bsum[blockIdx.x] = woff + inc;
}

__global__ void k_addoff() {
    __shared__ int red[4];
    __shared__ int boff;
    int t = threadIdx.x;
    int bid = blockIdx.x;
    int partial = 0;
    for (int j = t; j < bid; j += 128) partial += g_bsum[j];
    int lane = t & 31, w = t >> 5;
    #pragma unroll
    for (int s = 16; s > 0; s >>= 1)
        partial += __shfl_down_sync(0xffffffffu, partial, s);
    if (lane == 0) red[w] = partial;
    __syncthreads();
    if (t == 0) boff = red[0] + red[1] + red[2] + red[3];
    __syncthreads();
    int i = bid * 128 + t;
    if (i < N_NODES) g_off[i] += boff;
    if (i == 0) g_off[N_NODES] = N_EDGES;
}

// fill CSR, consuming g_cnt as the per-node cursor (counts down)
__global__ void k_fill(const void* __restrict__ eidx) {
    int e = blockIdx.x * blockDim.x + threadIdx.x;
    if (e < N_EDGES) {
        int r = idx_at(eidx, e, N_NODES - 1);
        int c = idx_at(eidx, (long long)N_EDGES + e, N_NODES - 1);
        int pos = g_off[c] + atomicAdd(&g_cnt[c], -1) - 1;
        if (pos >= 0 && pos < N_EDGES) g_csr[pos] = r;
    }
}

// ---------------- compute -----------------------------------------------------

// g_hh = (X*dinv) @ W_gcn (wmma, 64 rows/block, 8 warps, half-frag direct store)
__global__ void __launch_bounds__(256) k_gemm1(const float* __restrict__ X) {
    __shared__ __align__(16) __half xa[GROWS][HID];   // 16KB
    __shared__ __align__(16) __half wb[16][HID];      // 4KB k-chunk
    int r0 = blockIdx.x * GROWS;
    int tid = threadIdx.x;
    int warp = tid >> 5;
    int wr = warp & 3, wc = warp >> 2;   // row group (16), col half (64)

    // A tile: fold dinv into A. 64 rows x 32 float4
    #pragma unroll 4
    for (int i = 0; i < 8; i++) {
        int idx = tid + i * 256;
        int r = idx >> 5, c4 = idx & 31;
        int gr = r0 + r;
        float4 v = make_float4(0.f, 0.f, 0.f, 0.f);
        float dv = 0.f;
        if (gr < N_NODES) {
            v = ((const float4*)X)[(size_t)gr * 32 + c4];
            dv = g_dinv[gr];
        }
        __half2* dst = (__half2*)&xa[r][c4 * 4];
        dst[0] = __floats2half2_rn(v.x * dv, v.y * dv);
        dst[1] = __floats2half2_rn(v.z * dv, v.w * dv);
    }

    wmma::fragment<wmma::accumulator, 16, 16, 16, float> cf[4];
    #pragma unroll
    for (int j = 0; j < 4; j++) wmma::fill_fragment(cf[j], 0.f);

    for (int kc = 0; kc < 8; kc++) {
        __syncthreads();
        ((uint4*)wb)[tid] = ((const uint4*)(g_wgcn16 + kc * 16 * HID))[tid];
        __syncthreads();
        wmma::fragment<wmma::matrix_a, 16, 16, 16, __half, wmma::row_major> af;
        wmma::load_matrix_sync(af, &xa[wr * 16][kc * 16], HID);
        #pragma unroll
        for (int j = 0; j < 4; j++) {
            wmma::fragment<wmma::matrix_b, 16, 16, 16, __half, wmma::row_major> bf;
            wmma::load_matrix_sync(bf, &wb[0][wc * 64 + j * 16], HID);
            wmma::mma_sync(cf[j], af, bf, cf[j]);
        }
    }

    int rowg = r0 + wr * 16;
    if (rowg + 16 <= N_NODES) {          // N_NODES % 16 == 0
        #pragma unroll
        for (int j = 0; j < 4; j++) {
            wmma::fragment<wmma::accumulator, 16, 16, 16, __half> hf;
            #pragma unroll
            for (int i = 0; i < hf.num_elements; i++)
                hf.x[i] = __float2half_rn(cf[j].x[i]);
            wmma::store_matrix_sync(&g_hh[(size_t)rowg * HID + wc * 64 + j * 16],
                                    hf, HID, wmma::mem_row_major);
        }
    }
}

// GCN gather (fp16 rows, fp32 accum, 8-deep MLP)
__global__ void k_gcn_agg(const float* __restrict__ b_gcn) {
    int warp = (blockIdx.x * blockDim.x + threadIdx.x) >> 5;
    int lane = threadIdx.x & 31;
    if (warp >= N_NODES) return;
    int v = warp;
    float dv = g_dinv[v];
    const half4_t* base = (const half4_t*)g_hh;
    float4 acc = make_float4(0.f, 0.f, 0.f, 0.f);
    acc4(acc, base[(size_t)v * 32 + lane]);
    int beg = g_off[v], end = g_off[v + 1];
    int i = beg;
    for (; i + 8 <= end; i += 8) {
        int s0 = g_csr[i],     s1 = g_csr[i + 1], s2 = g_csr[i + 2], s3 = g_csr[i + 3];
        int s4 = g_csr[i + 4], s5 = g_csr[i + 5], s6 = g_csr[i + 6], s7 = g_csr[i + 7];
        half4_t a = base[(size_t)s0 * 32 + lane];
        half4_t b = base[(size_t)s1 * 32 + lane];
        half4_t c = base[(size_t)s2 * 32 + lane];
        half4_t d = base[(size_t)s3 * 32 + lane];
        half4_t e = base[(size_t)s4 * 32 + lane];
        half4_t f = base[(size_t)s5 * 32 + lane];
        half4_t g = base[(size_t)s6 * 32 + lane];
        half4_t h = base[(size_t)s7 * 32 + lane];
        acc4(acc, a); acc4(acc, b); acc4(acc, c); acc4(acc, d);
        acc4(acc, e); acc4(acc, f); acc4(acc, g); acc4(acc, h);
    }
    for (; i < end; i++) acc4(acc, base[(size_t)g_csr[i] * 32 + lane]);
    float4 b4 = ((const float4*)b_gcn)[lane];
    float r0 = fmaxf(fmaf(acc.x, dv, b4.x), 0.f);
    float r1 = fmaxf(fmaf(acc.y, dv, b4.y), 0.f);
    float r2 = fmaxf(fmaf(acc.z, dv, b4.z), 0.f);
    float r3 = fmaxf(fmaf(acc.w, dv, b4.w), 0.f);
    half4_t o;
    o.a = __floats2half2_rn(r0, r1);
    o.b = __floats2half2_rn(r2, r3);
    ((half4_t*)g_hgcnh)[(size_t)v * 32 + lane] = o;
}

// fused: SAGE mean gather + wmma dual-GEMM + bias + relu + pool
// 64 rows/block, 256 threads, smem union for epilogue
__global__ void __launch_bounds__(256) k_gemm2(const float* __restrict__ b,
                                               const void* __restrict__ batch) {
    __shared__ __align__(16) char smpool[16384 + 16384 + 4096 + 4096 + 256];
    __half (*hsa)[HID] = (__half(*)[HID])(smpool);           // 16KB
    __half (*nsa)[HID] = (__half(*)[HID])(smpool + 16384);   // 16KB
    __half (*wlb)[HID] = (__half(*)[HID])(smpool + 32768);   // 4KB
    __half (*wrb)[HID] = (__half(*)[HID])(smpool + 36864);   // 4KB
    int* bg = (int*)(smpool + 40960);                        // 256B
    float (*outb)[HID] = (float(*)[HID])(smpool);            // 32KB (reuse hsa+nsa)

    int r0 = blockIdx.x * GROWS;
    int tid = threadIdx.x;
    int warp = tid >> 5, lane = tid & 31;
    int wr = warp & 3, wc = warp >> 2;

    // copy h_gcn tile (fp16 already): 64 rows x 16 uint4
    #pragma unroll 4
    for (int i = 0; i < 4; i++) {
        int idx = tid + i * 256;
        int r = idx >> 4, c = idx & 15;
        uint4 v = make_uint4(0u, 0u, 0u, 0u);
        if (r0 + r < N_NODES)
            v = ((const uint4*)(g_hgcnh + (size_t)(r0 + r) * HID))[c];
        ((uint4*)&hsa[r][0])[c] = v;
    }
    if (tid < 64) bg[tid] = idx_at(batch, clampi(r0 + tid, 0, N_NODES - 1), N_GRAPHS - 1);

    // gather mean(neigh) for 8 nodes per warp
    const half4_t* base = (const half4_t*)g_hgcnh;
    #pragma unroll
    for (int j = 0; j < 8; j++) {
        int r = warp * 8 + j;
        int v = r0 + r;
        half4_t o;
        if (v < N_NODES) {
            float4 acc = make_float4(0.f, 0.f, 0.f, 0.f);
            int beg = g_off[v], end = g_off[v + 1];
            int i = beg;
            for (; i + 8 <= end; i += 8) {
                int s0 = g_csr[i],     s1 = g_csr[i + 1], s2 = g_csr[i + 2], s3 = g_csr[i + 3];
                int s4 = g_csr[i + 4], s5 = g_csr[i + 5], s6 = g_csr[i + 6], s7 = g_csr[i + 7];
                half4_t a0 = base[(size_t)s0 * 32 + lane];
                half4_t a1 = base[(size_t)s1 * 32 + lane];
                half4_t a2 = base[(size_t)s2 * 32 + lane];
                half4_t a3 = base[(size_t)s3 * 32 + lane];
                half4_t a4 = base[(size_t)s4 * 32 + lane];
                half4_t a5 = base[(size_t)s5 * 32 + lane];
                half4_t a6 = base[(size_t)s6 * 32 + lane];
                half4_t a7 = base[(size_t)s7 * 32 + lane];
                acc4(acc, a0); acc4(acc, a1); acc4(acc, a2); acc4(acc, a3);
                acc4(acc, a4); acc4(acc, a5); acc4(acc, a6); acc4(acc, a7);
            }
            for (; i < end; i++) acc4(acc, base[(size_t)g_csr[i] * 32 + lane]);
            float inv = 1.f / fmaxf((float)(end - beg), 1.f);
            o.a = __floats2half2_rn(acc.x * inv, acc.y * inv);
            o.b = __floats2half2_rn(acc.z * inv, acc.w * inv);
        } else {
            o.a = __floats2half2_rn(0.f, 0.f);
            o.b = __floats2half2_rn(0.f, 0.f);
        }
        ((half4_t*)&nsa[r][0])[lane] = o;
    }

    wmma::fragment<wmma::accumulator, 16, 16, 16, float> cf[4];
    #pragma unroll
    for (int j = 0; j < 4; j++) wmma::fill_fragment(cf[j], 0.f);

    for (int kc = 0; kc < 8; kc++) {
        __syncthreads();
        ((uint4*)wlb)[tid] = ((const uint4*)(g_wl16 + kc * 16 * HID))[tid];
        ((uint4*)wrb)[tid] = ((const uint4*)(g_wr16 + kc * 16 * HID))[tid];
        __syncthreads();
        wmma::fragment<wmma::matrix_a, 16, 16, 16, __half, wmma::row_major> an, ah;
        wmma::load_matrix_sync(an, &nsa[wr * 16][kc * 16], HID);
        wmma::load_matrix_sync(ah, &hsa[wr * 16][kc * 16], HID);
        #pragma unroll
        for (int j = 0; j < 4; j++) {
            wmma::fragment<wmma::matrix_b, 16, 16, 16, __half, wmma::row_major> bf;
            wmma::load_matrix_sync(bf, &wlb[0][wc * 64 + j * 16], HID);
            wmma::mma_sync(cf[j], an, bf, cf[j]);
            wmma::load_matrix_sync(bf, &wrb[0][wc * 64 + j * 16], HID);
            wmma::mma_sync(cf[j], ah, bf, cf[j]);
        }
    }
    __syncthreads();   // all mma reads of hsa/nsa done -> safe to overwrite (outb)
    #pragma unroll
    for (int j = 0; j < 4; j++)
        wmma::store_matrix_sync(&outb[wr * 16][wc * 64 + j * 16], cf[j],
                                HID, wmma::mem_row_major);
    __syncthreads();

    // epilogue: bias + relu + fused pool (batch sorted -> run accumulate)
    int col = tid & 127, seg = tid >> 7;    // 2 threads/col, 32 rows each
    float bt = b[col];
    float psum = 0.f;
    int cur = bg[seg * 32];
    for (int r = seg * 32; r < seg * 32 + 32; r++) {
        if (r0 + r >= N_NODES) break;
        int g = bg[r];
        if (g != cur) {
            atomicAdd(&g_pooled[cur * HID + col], psum);
            psum = 0.f; cur = g;
        }
        psum += fmaxf(outb[r][col] + bt, 0.f);
    }
    atomicAdd(&g_pooled[cur * HID + col], psum);
}

// MLP head
__global__ void k_head(const float* __restrict__ Wfc1, const float* __restrict__ b1,
                       const float* __restrict__ Wfc2, const float* __restrict__ b2,
                       float* __restrict__ out) {
    __shared__ float hid[HID];
    int g = blockIdx.x;
    int t = threadIdx.x;
    float acc = b1[t];
    #pragma unroll 8
    for (int k = 0; k < HID; k++)
        acc = fmaf(g_pooled[g * HID + k], Wfc1[k * HID + t], acc);
    hid[t] = fmaxf(acc, 0.f);
    __syncthreads();
    if (t < OUT_DIM) {
        float o = b2[t];
        #pragma unroll 8
        for (int k = 0; k < HID; k++)
            o = fmaf(hid[k], Wfc2[k * OUT_DIM + t], o);
        out[g * OUT_DIM + t] = o;
    }
}

// ---------------- launch ------------------------------------------------------
extern "C" void kernel_launch(void* const* d_in, const int* in_sizes, int n_in,
                              void* d_out, int out_size) {
    int map[12] = {0,1,2,3,4,5,6,7,8,9,10,11};
    if (n_in >= 12 && in_sizes[0] != 2560000) {
        const int alpha[12] = {11, 10,  9,  2,  7,  3,  4,  8,  0,  5,  1,  6};
        for (int i = 0; i < 12; i++) map[i] = alpha[i];
    }
    const float* x      = (const float*)d_in[map[0]];
    const void*  eidx   = d_in[map[1]];
    const void*  batch  = d_in[map[2]];
    const float* W_gcn  = (const float*)d_in[map[3]];
    const float* b_gcn  = (const float*)d_in[map[4]];
    const float* W_sl   = (const float*)d_in[map[5]];
    const float* W_sr   = (const float*)d_in[map[6]];
    const float* b_sage = (const float*)d_in[map[7]];
    const float* W_fc1  = (const float*)d_in[map[8]];
    const float* b_fc1  = (const float*)d_in[map[9]];
    const float* W_fc2  = (const float*)d_in[map[10]];
    const float* b_fc2  = (const float*)d_in[map[11]];
    float* out = (float*)d_out;

    k_init<<<160, 256>>>((const int*)eidx, W_gcn, W_sl, W_sr);  // 1
    k_count<<<(N_EDGES + 255) / 256, 256>>>(eidx);              // 2
    k_blockscan<<<NBLK, 128>>>();                               // 3 (also dinv)
    k_gemm1<<<GRID_G, 256>>>(x);                                // 4 <- profiled
    k_addoff<<<NBLK, 128>>>();                                  // 5
    k_fill<<<(N_EDGES + 255) / 256, 256>>>(eidx);               // 6
    k_gcn_agg<<<(N_NODES * 32 + 255) / 256, 256>>>(b_gcn);      // 7
    k_gemm2<<<GRID_G, 256>>>(b_sage, batch);                    // 8
    k_head<<<N_GRAPHS, HID>>>(W_fc1, b_fc1, W_fc2, b_fc2, out);
}